// round 5
// baseline (speedup 1.0000x reference)
#include <cuda_runtime.h>

// Problem constants
#define NB    2
#define NT    2048
#define ND    1024
#define NH    16
#define DH    64
#define NMEM  512
#define NKV   2560      // MEM + T

#define LOG2E 1.4426950408889634f

// Per-batch scratch (allocation-free __device__ globals, 32 MB total)
__device__ float g_q[NH*NT*DH];   // [h][t][c]  8MB
__device__ float g_k[NH*NT*DH];   //            8MB
__device__ float g_v[NH*NT*DH];   //            8MB
__device__ float g_ob[NT*ND];     // attention output of one batch, [t][d] 8MB

// ---------------------------------------------------------------------------
// Shared 128x128x16 fp32 GEMM core: C[128,128] tile of A[M,K] * B[N,K]^T
// (both operands row-major, K contiguous). 256 threads, 8x8 per thread with
// split 4+4 row/col mapping for conflict-free float4 smem reads.
// ---------------------------------------------------------------------------
__device__ __forceinline__ void gemm_tile_128(
    const float* __restrict__ A, const float* __restrict__ B, int K,
    float (&acc)[8][8])
{
    __shared__ float As[16][132];   // [k][m], +4 pad
    __shared__ float Bs[16][132];   // [k][n]

    const int tid  = threadIdx.x;
    const int tx   = tid & 15;
    const int ty   = tid >> 4;
    const int lrow = tid >> 2;          // 0..63
    const int lcol = (tid & 3) << 2;    // 0,4,8,12
    const int bm   = blockIdx.x;
    const int bn   = blockIdx.y;

    #pragma unroll
    for (int i = 0; i < 8; i++)
        #pragma unroll
        for (int j = 0; j < 8; j++) acc[i][j] = 0.f;

    const float* Ap = A + (size_t)(bm*128 + lrow)*K + lcol;
    const float* Bp = B + (size_t)(bn*128 + lrow)*K + lcol;

    for (int k0 = 0; k0 < K; k0 += 16) {
        #pragma unroll
        for (int i = 0; i < 2; i++) {
            int r = lrow + i*64;
            float4 av = *(const float4*)(Ap + (size_t)i*64*K + k0);
            As[lcol+0][r] = av.x; As[lcol+1][r] = av.y;
            As[lcol+2][r] = av.z; As[lcol+3][r] = av.w;
            float4 bv = *(const float4*)(Bp + (size_t)i*64*K + k0);
            Bs[lcol+0][r] = bv.x; Bs[lcol+1][r] = bv.y;
            Bs[lcol+2][r] = bv.z; Bs[lcol+3][r] = bv.w;
        }
        __syncthreads();
        #pragma unroll
        for (int k = 0; k < 16; k++) {
            float a[8], b[8];
            *(float4*)(a)     = *(const float4*)&As[k][ty*4];
            *(float4*)(a + 4) = *(const float4*)&As[k][64 + ty*4];
            *(float4*)(b)     = *(const float4*)&Bs[k][tx*4];
            *(float4*)(b + 4) = *(const float4*)&Bs[k][64 + tx*4];
            #pragma unroll
            for (int i = 0; i < 8; i++)
                #pragma unroll
                for (int j = 0; j < 8; j++)
                    acc[i][j] = fmaf(a[i], b[j], acc[i][j]);
        }
        __syncthreads();
    }
}

// ---------------------------------------------------------------------------
// Kernel 1 (per batch): QKV projection, scatter epilogue into [h][t][c]
// X = x + b*NT*ND.  Grid (NT/128, 3*ND/128) = (16, 24), 256 threads.
// ---------------------------------------------------------------------------
__global__ __launch_bounds__(256, 2) void qkv_gemm_kernel(
    const float* __restrict__ X, const float* __restrict__ W)
{
    float acc[8][8];
    gemm_tile_128(X, W, ND, acc);

    const int tx = threadIdx.x & 15;
    const int ty = threadIdx.x >> 4;
    const int bm = blockIdx.x, bn = blockIdx.y;

    #pragma unroll
    for (int i = 0; i < 8; i++) {
        int t = bm*128 + ((i < 4) ? ty*4 + i : 64 + ty*4 + i - 4);
        #pragma unroll
        for (int j = 0; j < 8; j++) {
            int gcol   = bn*128 + ((j < 4) ? tx*4 + j : 64 + tx*4 + j - 4);
            int sec    = gcol >> 10;      // 0=q,1=k,2=v
            int within = gcol & 1023;
            int h      = within >> 6;
            int c      = within & 63;
            size_t idx = ((size_t)h*NT + t)*DH + c;
            float v = acc[i][j];
            if (sec == 0)      g_q[idx] = v;
            else if (sec == 1) g_k[idx] = v;
            else               g_v[idx] = v;
        }
    }
}

// ---------------------------------------------------------------------------
// Kernel 2 (per batch): flash attention (fp32). Grid (T/64, H), 128 threads.
// Memory K/V (first 512 keys == first 8 key-tiles) read directly from
// `memory` — the concat is never materialized. scale*log2e folded into Q.
// ---------------------------------------------------------------------------
#define ATTN_SMEM_FLOATS (64*64 + 64*65 + 64*64 + 64*64)
#define ATTN_SMEM_BYTES  (ATTN_SMEM_FLOATS * 4)

__global__ __launch_bounds__(128, 3) void attn_kernel(
    const float* __restrict__ memory)
{
    extern __shared__ float sm[];
    float* Qs = sm;                 // [row][d]   stride 64
    float* Ks = sm + 64*64;         // [d][key]   stride 65 (conflict-free key reads)
    float* Vs = Ks + 64*65;         // [key][d]   stride 64
    float* Ps = Vs + 64*64;         // [row][key] stride 64

    const int tid  = threadIdx.x;
    const int lane = tid & 31;
    const int warp = tid >> 5;
    const int qt   = blockIdx.x;
    const int h    = blockIdx.y;
    const int r0   = warp * 16;     // this warp's 16 query rows

    // Load + scale Q tile
    {
        const float qsc = 0.125f * LOG2E;   // hd^-0.5 * log2(e)
        int row = tid >> 1;
        int d0  = (tid & 1) * 32;
        const float* src = g_q + ((size_t)h*NT + (size_t)qt*64 + row)*DH + d0;
        float* dst = Qs + row*64 + d0;
        #pragma unroll
        for (int i = 0; i < 8; i++) {
            float4 v = *(const float4*)(src + i*4);
            v.x *= qsc; v.y *= qsc; v.z *= qsc; v.w *= qsc;
            *(float4*)(dst + i*4) = v;
        }
    }

    float O[16][2], m[16], l[16];
    #pragma unroll
    for (int j = 0; j < 16; j++) {
        O[j][0] = 0.f; O[j][1] = 0.f;
        m[j] = -1e30f; l[j] = 0.f;
    }

    for (int kt = 0; kt < NKV/64; kt++) {
        __syncthreads();   // previous PV done in all warps before overwrite
        // Load K (transposed) and V tiles
        {
            int key = tid >> 1;
            int d0  = (tid & 1) * 32;
            const float *kb, *vb;
            if (kt < NMEM/64) {
                kb = memory + ((size_t)(kt*64 + key))*ND + h*DH + d0;
                vb = kb;   // k and v both come from `memory` for the first 512 keys
            } else {
                size_t off = ((size_t)h*NT + (size_t)(kt*64 - NMEM) + key)*DH + d0;
                kb = g_k + off;
                vb = g_v + off;
            }
            #pragma unroll
            for (int i = 0; i < 8; i++) {
                float4 kv = *(const float4*)(kb + i*4);
                Ks[(d0 + i*4 + 0)*65 + key] = kv.x;
                Ks[(d0 + i*4 + 1)*65 + key] = kv.y;
                Ks[(d0 + i*4 + 2)*65 + key] = kv.z;
                Ks[(d0 + i*4 + 3)*65 + key] = kv.w;
                *(float4*)(Vs + key*64 + d0 + i*4) = *(const float4*)(vb + i*4);
            }
        }
        __syncthreads();

        // S = Q K^T (lane owns keys {lane, lane+32}, warp owns 16 rows)
        float S[16][2];
        #pragma unroll
        for (int j = 0; j < 16; j++) { S[j][0] = 0.f; S[j][1] = 0.f; }
        #pragma unroll 2
        for (int d = 0; d < 64; d += 4) {
            float ka[4], kb2[4];
            #pragma unroll
            for (int dd = 0; dd < 4; dd++) {
                ka[dd]  = Ks[(d+dd)*65 + lane];
                kb2[dd] = Ks[(d+dd)*65 + lane + 32];
            }
            #pragma unroll
            for (int j = 0; j < 16; j++) {
                float4 q = *(const float4*)(Qs + (r0 + j)*64 + d);
                S[j][0] += q.x*ka[0]  + q.y*ka[1]  + q.z*ka[2]  + q.w*ka[3];
                S[j][1] += q.x*kb2[0] + q.y*kb2[1] + q.z*kb2[2] + q.w*kb2[3];
            }
        }

        // Online softmax (base-2)
        #pragma unroll
        for (int j = 0; j < 16; j++) {
            float mx = fmaxf(S[j][0], S[j][1]);
            #pragma unroll
            for (int o = 16; o > 0; o >>= 1)
                mx = fmaxf(mx, __shfl_xor_sync(0xffffffffu, mx, o));
            float mnew  = fmaxf(m[j], mx);
            float alpha = exp2f(m[j] - mnew);
            float p0 = exp2f(S[j][0] - mnew);
            float p1 = exp2f(S[j][1] - mnew);
            float rs = p0 + p1;
            #pragma unroll
            for (int o = 16; o > 0; o >>= 1)
                rs += __shfl_xor_sync(0xffffffffu, rs, o);
            l[j] = l[j]*alpha + rs;
            m[j] = mnew;
            O[j][0] *= alpha; O[j][1] *= alpha;
            Ps[(r0+j)*64 + lane]      = p0;
            Ps[(r0+j)*64 + lane + 32] = p1;
        }
        __syncwarp();

        // O += P V (lane owns cols {2*lane, 2*lane+1})
        #pragma unroll 2
        for (int key = 0; key < 64; key++) {
            float2 vv = *(const float2*)(Vs + key*64 + 2*lane);
            #pragma unroll
            for (int j = 0; j < 16; j++) {
                float p = Ps[(r0+j)*64 + key];
                O[j][0] += p * vv.x;
                O[j][1] += p * vv.y;
            }
        }
    }

    // Normalize and write out in [t][d] layout (ready for out-proj GEMM)
    #pragma unroll
    for (int j = 0; j < 16; j++) {
        float inv = 1.0f / l[j];
        int row = qt*64 + r0 + j;
        float2 o2 = make_float2(O[j][0]*inv, O[j][1]*inv);
        *(float2*)(g_ob + (size_t)row*ND + h*DH + 2*lane) = o2;
    }
}

// ---------------------------------------------------------------------------
// Kernel 3 (per batch): output projection + bias into this batch's d_out rows
// Grid (NT/128, ND/128) = (16, 8), 256 threads.
// ---------------------------------------------------------------------------
__global__ __launch_bounds__(256, 2) void out_gemm_kernel(
    const float* __restrict__ W, const float* __restrict__ bias,
    float* __restrict__ Yb)
{
    float acc[8][8];
    gemm_tile_128(g_ob, W, ND, acc);

    const int tx = threadIdx.x & 15;
    const int ty = threadIdx.x >> 4;
    const int bm = blockIdx.x, bn = blockIdx.y;

    #pragma unroll
    for (int i = 0; i < 8; i++) {
        int grow = bm*128 + ((i < 4) ? ty*4 + i : 64 + ty*4 + i - 4);
        #pragma unroll
        for (int j = 0; j < 8; j++) {
            int gcol = bn*128 + ((j < 4) ? tx*4 + j : 64 + tx*4 + j - 4);
            Yb[(size_t)grow*ND + gcol] = acc[i][j] + bias[gcol];
        }
    }
}

// ---------------------------------------------------------------------------
extern "C" void kernel_launch(void* const* d_in, const int* in_sizes, int n_in,
                              void* d_out, int out_size)
{
    // Identify inputs by element count (robust to ordering):
    //   x 4194304, w_qkv 3145728, w_out 1048576, b_out 1024, memory 524288
    const float *x = nullptr, *w_qkv = nullptr, *w_out = nullptr,
                *b_out = nullptr, *memory = nullptr;
    for (int i = 0; i < n_in; i++) {
        switch (in_sizes[i]) {
            case 4194304: x      = (const float*)d_in[i]; break;
            case 3145728: w_qkv  = (const float*)d_in[i]; break;
            case 1048576: w_out  = (const float*)d_in[i]; break;
            case 1024:    b_out  = (const float*)d_in[i]; break;
            case 524288:  memory = (const float*)d_in[i]; break;
            default: break;
        }
    }
    float* out = (float*)d_out;

    cudaFuncSetAttribute(attn_kernel,
                         cudaFuncAttributeMaxDynamicSharedMemorySize,
                         ATTN_SMEM_BYTES);

    // Per-batch pipeline over shared scratch; stream order serializes reuse.
    for (int b = 0; b < NB; b++) {
        const float* xb = x + (size_t)b*NT*ND;
        float*       yb = out + (size_t)b*NT*ND;
        qkv_gemm_kernel<<<dim3(NT/128, 3*ND/128), 256>>>(xb, w_qkv);        // 16 x 24
        attn_kernel<<<dim3(NT/64, NH), 128, ATTN_SMEM_BYTES>>>(memory);     // 32 x 16
        out_gemm_kernel<<<dim3(NT/128, ND/128), 256>>>(w_out, b_out, yb);   // 16 x 8
    }
}

// round 7
// speedup vs baseline: 1.2115x; 1.2115x over previous
#include <cuda_runtime.h>
#include <cuda_bf16.h>
#include <cstdint>

// Problem constants
#define NB    2
#define NT    2048
#define ND    1024
#define NH    16
#define DH    64
#define NMEM  512
#define NKV   2560      // MEM + T

#define LOG2E 1.4426950408889634f

// Per-batch scratch (allocation-free __device__ globals, 32 MB total)
__device__ float g_q[NH*NT*DH];   // [h][t][c]  8MB
__device__ float g_k[NH*NT*DH];
__device__ float g_v[NH*NT*DH];
__device__ float g_ob[NT*ND];     // attention output of one batch, [t][d]

// ===========================================================================
// bf16 helpers (family-portable; no tcgen05 anywhere in this file)
// ===========================================================================
__device__ __forceinline__ uint32_t pack_bf16x2(float lo, float hi) {
    // returns register with .lo = bf16(lo), .hi = bf16(hi)
    __nv_bfloat162 h = __float22bfloat162_rn(make_float2(lo, hi));
    return *reinterpret_cast<uint32_t*>(&h);
}
__device__ __forceinline__ float bf16lo_to_f32(uint32_t p) {
    return __uint_as_float(p << 16);
}
__device__ __forceinline__ float bf16hi_to_f32(uint32_t p) {
    return __uint_as_float(p & 0xffff0000u);
}

// mma.sync m16n8k16 row.col f32.bf16.bf16.f32  (sm_80+, family-portable)
__device__ __forceinline__ void mma_bf16(float (&c)[4],
                                         const uint32_t (&a)[4],
                                         const uint32_t (&b)[2]) {
    asm volatile(
        "mma.sync.aligned.m16n8k16.row.col.f32.bf16.bf16.f32 "
        "{%0,%1,%2,%3}, {%4,%5,%6,%7}, {%8,%9}, {%0,%1,%2,%3};"
        : "+f"(c[0]), "+f"(c[1]), "+f"(c[2]), "+f"(c[3])
        : "r"(a[0]), "r"(a[1]), "r"(a[2]), "r"(a[3]),
          "r"(b[0]), "r"(b[1]));
}

// ===========================================================================
// Split-bf16 tensor-core GEMM core.
// C[128,128] tile (bm, bn) of A[M,K] * B[N,K]^T, both row-major K-contiguous.
// 256 threads, 8 warps as 2 (m) x 4 (n); warp tile 64x32.
// K staged in 32-float chunks; smem holds bf16x2-packed hi/lo tiles.
// Accumulators in registers: acc[mi][ni][4] (mi,ni = 0..3).
// ===========================================================================
#define SROW 20   // uint32 stride per row (16 pairs + 4 pad) -> conflict-free

struct GemmSmem {
    uint32_t Ahi[128*SROW];
    uint32_t Alo[128*SROW];
    uint32_t Bhi[128*SROW];
    uint32_t Blo[128*SROW];
};

__device__ __forceinline__ void gemm_bf16_core(
    const float* __restrict__ A, const float* __restrict__ B, int K,
    GemmSmem& s, float (&acc)[4][4][4])
{
    const int tid    = threadIdx.x;
    const int lane   = tid & 31;
    const int wid    = tid >> 5;
    const int warp_m = (wid & 1) * 64;

    #pragma unroll
    for (int mi = 0; mi < 4; mi++)
        #pragma unroll
        for (int ni = 0; ni < 4; ni++)
            #pragma unroll
            for (int r = 0; r < 4; r++) acc[mi][ni][r] = 0.f;

    const int lf4   = tid & 7;     // which float4 within 32-float chunk row
    const int rbase = tid >> 3;    // 0..31
    const float* Ap = A + (size_t)(blockIdx.x*128 + rbase)*K + lf4*4;
    const float* Bp = B + (size_t)(blockIdx.y*128 + rbase)*K + lf4*4;

    const int nchunks = K / 32;
    for (int c = 0; c < nchunks; c++) {
        __syncthreads();   // previous compute done before overwrite
        // ---- stage: fp32 -> bf16x2 hi/lo, 4 rows per thread per operand ----
        #pragma unroll
        for (int i = 0; i < 4; i++) {
            int row = i*32 + rbase;
            int so  = row*SROW + 2*lf4;
            float4 va = *(const float4*)(Ap + (size_t)(i*32)*K + c*32);
            uint32_t h0 = pack_bf16x2(va.x, va.y);
            uint32_t h1 = pack_bf16x2(va.z, va.w);
            uint32_t l0 = pack_bf16x2(va.x - bf16lo_to_f32(h0),
                                      va.y - bf16hi_to_f32(h0));
            uint32_t l1 = pack_bf16x2(va.z - bf16lo_to_f32(h1),
                                      va.w - bf16hi_to_f32(h1));
            *(uint2*)&s.Ahi[so] = make_uint2(h0, h1);
            *(uint2*)&s.Alo[so] = make_uint2(l0, l1);
            float4 vb = *(const float4*)(Bp + (size_t)(i*32)*K + c*32);
            h0 = pack_bf16x2(vb.x, vb.y);
            h1 = pack_bf16x2(vb.z, vb.w);
            l0 = pack_bf16x2(vb.x - bf16lo_to_f32(h0),
                             vb.y - bf16hi_to_f32(h0));
            l1 = pack_bf16x2(vb.z - bf16lo_to_f32(h1),
                             vb.w - bf16hi_to_f32(h1));
            *(uint2*)&s.Bhi[so] = make_uint2(h0, h1);
            *(uint2*)&s.Blo[so] = make_uint2(l0, l1);
        }
        __syncthreads();

        // ---- compute: 2 x k16 steps, 3 mma passes each ----
        const int warp_n = (wid >> 1) * 32;
        #pragma unroll
        for (int ks = 0; ks < 2; ks++) {
            const int colA = ks*8 + (lane & 3);
            const int rA   = warp_m + (lane >> 2);
            const int rB   = warp_n + (lane >> 2);

            uint32_t ah[4][4], al[4][4], bh[4][2], bl[4][2];
            #pragma unroll
            for (int mi = 0; mi < 4; mi++) {
                int r0 = (rA + mi*16)*SROW;
                int r1 = r0 + 8*SROW;
                ah[mi][0] = s.Ahi[r0 + colA];
                ah[mi][1] = s.Ahi[r1 + colA];
                ah[mi][2] = s.Ahi[r0 + colA + 4];
                ah[mi][3] = s.Ahi[r1 + colA + 4];
                al[mi][0] = s.Alo[r0 + colA];
                al[mi][1] = s.Alo[r1 + colA];
                al[mi][2] = s.Alo[r0 + colA + 4];
                al[mi][3] = s.Alo[r1 + colA + 4];
            }
            #pragma unroll
            for (int ni = 0; ni < 4; ni++) {
                int rn = (rB + ni*8)*SROW;
                bh[ni][0] = s.Bhi[rn + colA];
                bh[ni][1] = s.Bhi[rn + colA + 4];
                bl[ni][0] = s.Blo[rn + colA];
                bl[ni][1] = s.Blo[rn + colA + 4];
            }
            #pragma unroll
            for (int ni = 0; ni < 4; ni++)
                #pragma unroll
                for (int mi = 0; mi < 4; mi++)
                    mma_bf16(acc[mi][ni], ah[mi], bh[ni]);   // hi*hi
            #pragma unroll
            for (int ni = 0; ni < 4; ni++)
                #pragma unroll
                for (int mi = 0; mi < 4; mi++)
                    mma_bf16(acc[mi][ni], al[mi], bh[ni]);   // lo*hi
            #pragma unroll
            for (int ni = 0; ni < 4; ni++)
                #pragma unroll
                for (int mi = 0; mi < 4; mi++)
                    mma_bf16(acc[mi][ni], ah[mi], bl[ni]);   // hi*lo
        }
    }
}

// ---------------------------------------------------------------------------
// Kernel 1 (per batch): QKV projection, scatter epilogue into [h][t][c]
// Grid (NT/128, 3*ND/128) = (16, 24), 256 threads.
// ---------------------------------------------------------------------------
__global__ __launch_bounds__(256) void qkv_mma_kernel(
    const float* __restrict__ X, const float* __restrict__ W)
{
    __shared__ GemmSmem s;
    float acc[4][4][4];
    gemm_bf16_core(X, W, ND, s, acc);

    const int lane   = threadIdx.x & 31;
    const int wid    = threadIdx.x >> 5;
    const int warp_m = (wid & 1) * 64;
    const int warp_n = (wid >> 1) * 32;

    const int bn   = blockIdx.y;
    const int sec  = bn >> 3;                          // 0=q,1=k,2=v
    const int h    = (((bn & 7)*128) + warp_n) >> 6;   // constant per warp
    const int cbase= (warp_n & 32);
    float* gbuf = (sec == 0 ? g_q : sec == 1 ? g_k : g_v);

    #pragma unroll
    for (int mi = 0; mi < 4; mi++) {
        #pragma unroll
        for (int half = 0; half < 2; half++) {
            int t = blockIdx.x*128 + warp_m + mi*16 + (lane >> 2) + half*8;
            float* dst = gbuf + ((size_t)h*NT + t)*DH + cbase + 2*(lane & 3);
            #pragma unroll
            for (int ni = 0; ni < 4; ni++) {
                float2 v = make_float2(acc[mi][ni][2*half],
                                       acc[mi][ni][2*half + 1]);
                *(float2*)(dst + ni*8) = v;
            }
        }
    }
}

// ---------------------------------------------------------------------------
// Kernel 3 (per batch): output projection + bias into this batch's d_out rows
// Grid (NT/128, ND/128) = (16, 8), 256 threads.
// ---------------------------------------------------------------------------
__global__ __launch_bounds__(256) void out_mma_kernel(
    const float* __restrict__ W, const float* __restrict__ bias,
    float* __restrict__ Yb)
{
    __shared__ GemmSmem s;
    float acc[4][4][4];
    gemm_bf16_core(g_ob, W, ND, s, acc);

    const int lane   = threadIdx.x & 31;
    const int wid    = threadIdx.x >> 5;
    const int warp_m = (wid & 1) * 64;
    const int warp_n = (wid >> 1) * 32;

    const int ncol0 = blockIdx.y*128 + warp_n + 2*(lane & 3);
    float2 bset[4];
    #pragma unroll
    for (int ni = 0; ni < 4; ni++)
        bset[ni] = make_float2(bias[ncol0 + ni*8], bias[ncol0 + ni*8 + 1]);

    #pragma unroll
    for (int mi = 0; mi < 4; mi++) {
        #pragma unroll
        for (int half = 0; half < 2; half++) {
            int grow = blockIdx.x*128 + warp_m + mi*16 + (lane >> 2) + half*8;
            float* dst = Yb + (size_t)grow*ND + ncol0;
            #pragma unroll
            for (int ni = 0; ni < 4; ni++) {
                float2 v = make_float2(acc[mi][ni][2*half]   + bset[ni].x,
                                       acc[mi][ni][2*half+1] + bset[ni].y);
                *(float2*)(dst + ni*8) = v;
            }
        }
    }
}

// ---------------------------------------------------------------------------
// Kernel 2 (per batch): flash attention (fp32) — unchanged (known good).
// ---------------------------------------------------------------------------
#define ATTN_SMEM_FLOATS (64*64 + 64*65 + 64*64 + 64*64)
#define ATTN_SMEM_BYTES  (ATTN_SMEM_FLOATS * 4)

__global__ __launch_bounds__(128, 3) void attn_kernel(
    const float* __restrict__ memory)
{
    extern __shared__ float smf[];
    float* Qs = smf;                // [row][d]   stride 64
    float* Ks = smf + 64*64;        // [d][key]   stride 65
    float* Vs = Ks + 64*65;         // [key][d]   stride 64
    float* Ps = Vs + 64*64;         // [row][key] stride 64

    const int tid  = threadIdx.x;
    const int lane = tid & 31;
    const int warp = tid >> 5;
    const int qt   = blockIdx.x;
    const int h    = blockIdx.y;
    const int r0   = warp * 16;

    {
        const float qsc = 0.125f * LOG2E;
        int row = tid >> 1;
        int d0  = (tid & 1) * 32;
        const float* src = g_q + ((size_t)h*NT + (size_t)qt*64 + row)*DH + d0;
        float* dst = Qs + row*64 + d0;
        #pragma unroll
        for (int i = 0; i < 8; i++) {
            float4 v = *(const float4*)(src + i*4);
            v.x *= qsc; v.y *= qsc; v.z *= qsc; v.w *= qsc;
            *(float4*)(dst + i*4) = v;
        }
    }

    float O[16][2], m[16], l[16];
    #pragma unroll
    for (int j = 0; j < 16; j++) {
        O[j][0] = 0.f; O[j][1] = 0.f;
        m[j] = -1e30f; l[j] = 0.f;
    }

    for (int kt = 0; kt < NKV/64; kt++) {
        __syncthreads();
        {
            int key = tid >> 1;
            int d0  = (tid & 1) * 32;
            const float *kb, *vb;
            if (kt < NMEM/64) {
                kb = memory + ((size_t)(kt*64 + key))*ND + h*DH + d0;
                vb = kb;
            } else {
                size_t off = ((size_t)h*NT + (size_t)(kt*64 - NMEM) + key)*DH + d0;
                kb = g_k + off;
                vb = g_v + off;
            }
            #pragma unroll
            for (int i = 0; i < 8; i++) {
                float4 kv = *(const float4*)(kb + i*4);
                Ks[(d0 + i*4 + 0)*65 + key] = kv.x;
                Ks[(d0 + i*4 + 1)*65 + key] = kv.y;
                Ks[(d0 + i*4 + 2)*65 + key] = kv.z;
                Ks[(d0 + i*4 + 3)*65 + key] = kv.w;
                *(float4*)(Vs + key*64 + d0 + i*4) = *(const float4*)(vb + i*4);
            }
        }
        __syncthreads();

        float S[16][2];
        #pragma unroll
        for (int j = 0; j < 16; j++) { S[j][0] = 0.f; S[j][1] = 0.f; }
        #pragma unroll 2
        for (int d = 0; d < 64; d += 4) {
            float ka[4], kb2[4];
            #pragma unroll
            for (int dd = 0; dd < 4; dd++) {
                ka[dd]  = Ks[(d+dd)*65 + lane];
                kb2[dd] = Ks[(d+dd)*65 + lane + 32];
            }
            #pragma unroll
            for (int j = 0; j < 16; j++) {
                float4 q = *(const float4*)(Qs + (r0 + j)*64 + d);
                S[j][0] += q.x*ka[0]  + q.y*ka[1]  + q.z*ka[2]  + q.w*ka[3];
                S[j][1] += q.x*kb2[0] + q.y*kb2[1] + q.z*kb2[2] + q.w*kb2[3];
            }
        }

        #pragma unroll
        for (int j = 0; j < 16; j++) {
            float mx = fmaxf(S[j][0], S[j][1]);
            #pragma unroll
            for (int o = 16; o > 0; o >>= 1)
                mx = fmaxf(mx, __shfl_xor_sync(0xffffffffu, mx, o));
            float mnew  = fmaxf(m[j], mx);
            float alpha = exp2f(m[j] - mnew);
            float p0 = exp2f(S[j][0] - mnew);
            float p1 = exp2f(S[j][1] - mnew);
            float rs = p0 + p1;
            #pragma unroll
            for (int o = 16; o > 0; o >>= 1)
                rs += __shfl_xor_sync(0xffffffffu, rs, o);
            l[j] = l[j]*alpha + rs;
            m[j] = mnew;
            O[j][0] *= alpha; O[j][1] *= alpha;
            Ps[(r0+j)*64 + lane]      = p0;
            Ps[(r0+j)*64 + lane + 32] = p1;
        }
        __syncwarp();

        #pragma unroll 2
        for (int key = 0; key < 64; key++) {
            float2 vv = *(const float2*)(Vs + key*64 + 2*lane);
            #pragma unroll
            for (int j = 0; j < 16; j++) {
                float p = Ps[(r0+j)*64 + key];
                O[j][0] += p * vv.x;
                O[j][1] += p * vv.y;
            }
        }
    }

    #pragma unroll
    for (int j = 0; j < 16; j++) {
        float inv = 1.0f / l[j];
        int row = qt*64 + r0 + j;
        float2 o2 = make_float2(O[j][0]*inv, O[j][1]*inv);
        *(float2*)(g_ob + (size_t)row*ND + h*DH + 2*lane) = o2;
    }
}

// ---------------------------------------------------------------------------
extern "C" void kernel_launch(void* const* d_in, const int* in_sizes, int n_in,
                              void* d_out, int out_size)
{
    // Identify inputs by element count:
    //   x 4194304, w_qkv 3145728, w_out 1048576, b_out 1024, memory 524288
    const float *x = nullptr, *w_qkv = nullptr, *w_out = nullptr,
                *b_out = nullptr, *memory = nullptr;
    for (int i = 0; i < n_in; i++) {
        switch (in_sizes[i]) {
            case 4194304: x      = (const float*)d_in[i]; break;
            case 3145728: w_qkv  = (const float*)d_in[i]; break;
            case 1048576: w_out  = (const float*)d_in[i]; break;
            case 1024:    b_out  = (const float*)d_in[i]; break;
            case 524288:  memory = (const float*)d_in[i]; break;
            default: break;
        }
    }
    float* out = (float*)d_out;

    cudaFuncSetAttribute(attn_kernel,
                         cudaFuncAttributeMaxDynamicSharedMemorySize,
                         ATTN_SMEM_BYTES);

    // Per-batch pipeline over shared scratch; stream order serializes reuse.
    for (int b = 0; b < NB; b++) {
        const float* xb = x + (size_t)b*NT*ND;
        float*       yb = out + (size_t)b*NT*ND;
        qkv_mma_kernel<<<dim3(NT/128, 3*ND/128), 256>>>(xb, w_qkv);       // 16 x 24
        attn_kernel<<<dim3(NT/64, NH), 128, ATTN_SMEM_BYTES>>>(memory);   // 32 x 16
        out_mma_kernel<<<dim3(NT/128, ND/128), 256>>>(w_out, b_out, yb);  // 16 x 8
    }
}

// round 9
// speedup vs baseline: 1.8952x; 1.5643x over previous
#include <cuda_runtime.h>
#include <cuda_bf16.h>
#include <cstdint>

// Problem constants
#define NB    2
#define NT    2048
#define ND    1024
#define NH    16
#define DH    64
#define NMEM  512
#define NKV   2560      // MEM + T

#define LOG2E 1.4426950408889634f

// Per-batch scratch (allocation-free __device__ globals, ~37 MB total)
__device__ float    g_q  [NH*NT*DH];     // fp32 Q, [h][t][c]          8 MB
__device__ uint32_t g_khl[NH*NKV*DH];    // packed bf16 hi|lo K        10.5 MB
__device__ uint32_t g_vhl[NH*NKV*DH];    // packed bf16 hi|lo V        10.5 MB
__device__ float    g_ob [NT*ND];        // attention out, [t][d]      8 MB

// ===========================================================================
// bf16 helpers
// ===========================================================================
__device__ __forceinline__ uint32_t pack_bf16x2(float lo, float hi) {
    __nv_bfloat162 h = __float22bfloat162_rn(make_float2(lo, hi));
    return *reinterpret_cast<uint32_t*>(&h);
}
__device__ __forceinline__ float bf16lo_to_f32(uint32_t p) {
    return __uint_as_float(p << 16);
}
__device__ __forceinline__ float bf16hi_to_f32(uint32_t p) {
    return __uint_as_float(p & 0xffff0000u);
}
__device__ __forceinline__ uint32_t bf16bits(float v) {
    __nv_bfloat16 b = __float2bfloat16(v);
    return (uint32_t)*reinterpret_cast<unsigned short*>(&b);
}
// packed word: bf16(v) in top 16 bits, bf16(v - hi) in bottom 16 bits
__device__ __forceinline__ uint32_t packword(float v) {
    uint32_t hb = bf16bits(v);
    float hv = __uint_as_float(hb << 16);
    uint32_t lb = bf16bits(v - hv);
    return (hb << 16) | lb;
}
// combine two packed words into bf16x2 pairs of their hi / lo parts
__device__ __forceinline__ uint32_t hipair(uint32_t e0, uint32_t e1) {
    uint32_t r;
    asm("prmt.b32 %0,%1,%2,0x7632;" : "=r"(r) : "r"(e0), "r"(e1));
    return r;
}
__device__ __forceinline__ uint32_t lopair(uint32_t e0, uint32_t e1) {
    uint32_t r;
    asm("prmt.b32 %0,%1,%2,0x5410;" : "=r"(r) : "r"(e0), "r"(e1));
    return r;
}
// split two floats into hi bf16x2 and residual-lo bf16x2
__device__ __forceinline__ void split2(float x, float y,
                                       uint32_t& hi, uint32_t& lo) {
    uint32_t p = pack_bf16x2(x, y);
    lo = pack_bf16x2(x - bf16lo_to_f32(p), y - bf16hi_to_f32(p));
    hi = p;
}
__device__ __forceinline__ float ex2f(float x) {
    float r;
    asm("ex2.approx.ftz.f32 %0,%1;" : "=f"(r) : "f"(x));
    return r;
}

// mma.sync m16n8k16 row.col f32.bf16.bf16.f32  (family-portable)
__device__ __forceinline__ void mma_bf16(float (&c)[4],
                                         const uint32_t (&a)[4],
                                         const uint32_t (&b)[2]) {
    asm volatile(
        "mma.sync.aligned.m16n8k16.row.col.f32.bf16.bf16.f32 "
        "{%0,%1,%2,%3}, {%4,%5,%6,%7}, {%8,%9}, {%0,%1,%2,%3};"
        : "+f"(c[0]), "+f"(c[1]), "+f"(c[2]), "+f"(c[3])
        : "r"(a[0]), "r"(a[1]), "r"(a[2]), "r"(a[3]),
          "r"(b[0]), "r"(b[1]));
}

// ===========================================================================
// Split-bf16 tensor-core GEMM core (validated round 7).
// C[128,128] tile of A[M,K]*B[N,K]^T. 256 thr, 8 warps 2(m)x4(n), warp 64x32.
// ===========================================================================
#define SROW 20

struct GemmSmem {
    uint32_t Ahi[128*SROW];
    uint32_t Alo[128*SROW];
    uint32_t Bhi[128*SROW];
    uint32_t Blo[128*SROW];
};

__device__ __forceinline__ void gemm_bf16_core(
    const float* __restrict__ A, const float* __restrict__ B, int K,
    GemmSmem& s, float (&acc)[4][4][4])
{
    const int tid    = threadIdx.x;
    const int lane   = tid & 31;
    const int wid    = tid >> 5;
    const int warp_m = (wid & 1) * 64;

    #pragma unroll
    for (int mi = 0; mi < 4; mi++)
        #pragma unroll
        for (int ni = 0; ni < 4; ni++)
            #pragma unroll
            for (int r = 0; r < 4; r++) acc[mi][ni][r] = 0.f;

    const int lf4   = tid & 7;
    const int rbase = tid >> 3;
    const float* Ap = A + (size_t)(blockIdx.x*128 + rbase)*K + lf4*4;
    const float* Bp = B + (size_t)(blockIdx.y*128 + rbase)*K + lf4*4;

    const int nchunks = K / 32;
    for (int c = 0; c < nchunks; c++) {
        __syncthreads();
        #pragma unroll
        for (int i = 0; i < 4; i++) {
            int so = (i*32 + rbase)*SROW + 2*lf4;
            float4 va = *(const float4*)(Ap + (size_t)(i*32)*K + c*32);
            uint32_t h0, h1, l0, l1;
            split2(va.x, va.y, h0, l0);
            split2(va.z, va.w, h1, l1);
            *(uint2*)&s.Ahi[so] = make_uint2(h0, h1);
            *(uint2*)&s.Alo[so] = make_uint2(l0, l1);
            float4 vb = *(const float4*)(Bp + (size_t)(i*32)*K + c*32);
            split2(vb.x, vb.y, h0, l0);
            split2(vb.z, vb.w, h1, l1);
            *(uint2*)&s.Bhi[so] = make_uint2(h0, h1);
            *(uint2*)&s.Blo[so] = make_uint2(l0, l1);
        }
        __syncthreads();

        const int warp_n = (wid >> 1) * 32;
        #pragma unroll
        for (int ks = 0; ks < 2; ks++) {
            const int colA = ks*8 + (lane & 3);
            const int rA   = warp_m + (lane >> 2);
            const int rB   = warp_n + (lane >> 2);

            uint32_t ah[4][4], al[4][4], bh[4][2], bl[4][2];
            #pragma unroll
            for (int mi = 0; mi < 4; mi++) {
                int r0 = (rA + mi*16)*SROW;
                int r1 = r0 + 8*SROW;
                ah[mi][0] = s.Ahi[r0 + colA];
                ah[mi][1] = s.Ahi[r1 + colA];
                ah[mi][2] = s.Ahi[r0 + colA + 4];
                ah[mi][3] = s.Ahi[r1 + colA + 4];
                al[mi][0] = s.Alo[r0 + colA];
                al[mi][1] = s.Alo[r1 + colA];
                al[mi][2] = s.Alo[r0 + colA + 4];
                al[mi][3] = s.Alo[r1 + colA + 4];
            }
            #pragma unroll
            for (int ni = 0; ni < 4; ni++) {
                int rn = (rB + ni*8)*SROW;
                bh[ni][0] = s.Bhi[rn + colA];
                bh[ni][1] = s.Bhi[rn + colA + 4];
                bl[ni][0] = s.Blo[rn + colA];
                bl[ni][1] = s.Blo[rn + colA + 4];
            }
            #pragma unroll
            for (int ni = 0; ni < 4; ni++)
                #pragma unroll
                for (int mi = 0; mi < 4; mi++)
                    mma_bf16(acc[mi][ni], ah[mi], bh[ni]);
            #pragma unroll
            for (int ni = 0; ni < 4; ni++)
                #pragma unroll
                for (int mi = 0; mi < 4; mi++)
                    mma_bf16(acc[mi][ni], al[mi], bh[ni]);
            #pragma unroll
            for (int ni = 0; ni < 4; ni++)
                #pragma unroll
                for (int mi = 0; mi < 4; mi++)
                    mma_bf16(acc[mi][ni], ah[mi], bl[ni]);
        }
    }
}

// ---------------------------------------------------------------------------
// Kernel 0 (once): pack `memory` into K/V hi|lo buffers, keys [0, 512).
// ---------------------------------------------------------------------------
__global__ void pack_memory_kernel(const float* __restrict__ mem)
{
    int id = blockIdx.x*256 + threadIdx.x;     // 512*1024 total
    int key = id >> 10;
    int dg  = id & 1023;
    int h   = dg >> 6;
    int c   = dg & 63;
    uint32_t w = packword(mem[id]);
    size_t dst = ((size_t)h*NKV + key)*DH + c;
    g_khl[dst] = w;
    g_vhl[dst] = w;
}

// ---------------------------------------------------------------------------
// Kernel 1 (per batch): QKV projection; Q fp32 scatter, K/V packed hi|lo.
// Grid (16, 24), 256 threads.
// ---------------------------------------------------------------------------
__global__ __launch_bounds__(256) void qkv_mma_kernel(
    const float* __restrict__ X, const float* __restrict__ W)
{
    __shared__ GemmSmem s;
    float acc[4][4][4];
    gemm_bf16_core(X, W, ND, s, acc);

    const int lane   = threadIdx.x & 31;
    const int wid    = threadIdx.x >> 5;
    const int warp_m = (wid & 1) * 64;
    const int warp_n = (wid >> 1) * 32;

    const int bn    = blockIdx.y;
    const int sec   = bn >> 3;                          // 0=q,1=k,2=v
    const int h     = (((bn & 7)*128) + warp_n) >> 6;
    const int cbase = (warp_n & 32) + 2*(lane & 3);

    if (sec == 0) {
        #pragma unroll
        for (int mi = 0; mi < 4; mi++)
            #pragma unroll
            for (int half = 0; half < 2; half++) {
                int t = blockIdx.x*128 + warp_m + mi*16 + (lane >> 2) + half*8;
                float* dst = g_q + ((size_t)h*NT + t)*DH + cbase;
                #pragma unroll
                for (int ni = 0; ni < 4; ni++)
                    *(float2*)(dst + ni*8) =
                        make_float2(acc[mi][ni][2*half], acc[mi][ni][2*half+1]);
            }
    } else {
        uint32_t* gb = (sec == 1) ? g_khl : g_vhl;
        #pragma unroll
        for (int mi = 0; mi < 4; mi++)
            #pragma unroll
            for (int half = 0; half < 2; half++) {
                int t = blockIdx.x*128 + warp_m + mi*16 + (lane >> 2) + half*8;
                uint32_t* dst = gb + ((size_t)h*NKV + NMEM + t)*DH + cbase;
                #pragma unroll
                for (int ni = 0; ni < 4; ni++)
                    *(uint2*)(dst + ni*8) =
                        make_uint2(packword(acc[mi][ni][2*half]),
                                   packword(acc[mi][ni][2*half+1]));
            }
    }
}

// ---------------------------------------------------------------------------
// Kernel 2 (per batch): flash attention on tensor cores (split-bf16 mma).
// Grid (T/64, H) = (32, 16), 128 threads (4 warps x 16 q-rows).
// ---------------------------------------------------------------------------
#define KST 36    // smem stride (32 pairs + 4 pad)

__global__ __launch_bounds__(128, 3) void attn_mma_kernel()
{
    __shared__ uint32_t Khi[64*KST], Klo[64*KST];   // [key][d-pair]
    __shared__ uint32_t Vhi[64*KST], Vlo[64*KST];   // [d][key-pair]

    const int tid  = threadIdx.x;
    const int lane = tid & 31;
    const int warp = tid >> 5;
    const int qt   = blockIdx.x;
    const int h    = blockIdx.y;
    const int qr   = lane >> 2;      // quad row 0..7
    const int cq   = lane & 3;       // quad col 0..3

    // ---- stage Q (scaled, split) into Khi/Klo, then load A-fragments ----
    {
        const float qsc = 0.125f * LOG2E;
        int row = tid >> 1;
        int d0  = (tid & 1) * 32;
        const float* src = g_q + ((size_t)h*NT + qt*64 + row)*DH + d0;
        #pragma unroll
        for (int i = 0; i < 8; i++) {
            float4 v = *(const float4*)(src + i*4);
            uint32_t h0, h1, l0, l1;
            split2(v.x*qsc, v.y*qsc, h0, l0);
            split2(v.z*qsc, v.w*qsc, h1, l1);
            int so = row*KST + d0/2 + 2*i;
            *(uint2*)&Khi[so] = make_uint2(h0, h1);
            *(uint2*)&Klo[so] = make_uint2(l0, l1);
        }
    }
    __syncthreads();

    uint32_t qh[4][4], ql[4][4];
    {
        int r0 = (warp*16 + qr)*KST;
        int r1 = r0 + 8*KST;
        #pragma unroll
        for (int kb = 0; kb < 4; kb++) {
            int c0 = kb*8 + cq;
            qh[kb][0] = Khi[r0 + c0];     qh[kb][1] = Khi[r1 + c0];
            qh[kb][2] = Khi[r0 + c0 + 4]; qh[kb][3] = Khi[r1 + c0 + 4];
            ql[kb][0] = Klo[r0 + c0];     ql[kb][1] = Klo[r1 + c0];
            ql[kb][2] = Klo[r0 + c0 + 4]; ql[kb][3] = Klo[r1 + c0 + 4];
        }
    }

    float o[8][4];
    #pragma unroll
    for (int nb = 0; nb < 8; nb++)
        #pragma unroll
        for (int r = 0; r < 4; r++) o[nb][r] = 0.f;
    float mrow[2] = {-1e30f, -1e30f};
    float lrow[2] = {0.f, 0.f};

    const uint32_t* kbase = g_khl + (size_t)h*NKV*DH;
    const uint32_t* vbase = g_vhl + (size_t)h*NKV*DH;

    for (int kt = 0; kt < NKV/64; kt++) {
        __syncthreads();
        // ---- convert K tile: [key][d] words -> hi/lo bf16x2 d-pairs ----
        {
            const uint32_t* src = kbase + (size_t)(kt*64)*DH + 4*(tid & 15);
            int dp = 2*(tid & 15);
            #pragma unroll
            for (int j = 0; j < 8; j++) {
                int key = (tid >> 4) + j*8;
                uint4 e = *(const uint4*)(src + key*DH);
                int so = key*KST + dp;
                *(uint2*)&Khi[so] = make_uint2(hipair(e.x, e.y), hipair(e.z, e.w));
                *(uint2*)&Klo[so] = make_uint2(lopair(e.x, e.y), lopair(e.z, e.w));
            }
        }
        // ---- convert V tile transposed: [d][key-pair] ----
        {
            const uint32_t* src = vbase + (size_t)(kt*64)*DH + 4*(tid & 15);
            int d = 4*(tid & 15);
            #pragma unroll
            for (int j = 0; j < 4; j++) {
                int kp = (tid >> 4) + j*8;
                uint4 a = *(const uint4*)(src + (2*kp)*DH);
                uint4 b = *(const uint4*)(src + (2*kp + 1)*DH);
                Vhi[(d+0)*KST + kp] = hipair(a.x, b.x);
                Vhi[(d+1)*KST + kp] = hipair(a.y, b.y);
                Vhi[(d+2)*KST + kp] = hipair(a.z, b.z);
                Vhi[(d+3)*KST + kp] = hipair(a.w, b.w);
                Vlo[(d+0)*KST + kp] = lopair(a.x, b.x);
                Vlo[(d+1)*KST + kp] = lopair(a.y, b.y);
                Vlo[(d+2)*KST + kp] = lopair(a.z, b.z);
                Vlo[(d+3)*KST + kp] = lopair(a.w, b.w);
            }
        }
        __syncthreads();

        // ---- S = Q K^T (3-pass split) ----
        float s[8][4];
        #pragma unroll
        for (int nb = 0; nb < 8; nb++)
            #pragma unroll
            for (int r = 0; r < 4; r++) s[nb][r] = 0.f;
        #pragma unroll
        for (int kb = 0; kb < 4; kb++) {
            int c0 = kb*8 + cq;
            #pragma unroll
            for (int nb = 0; nb < 8; nb++) {
                int rk = (nb*8 + qr)*KST;
                uint32_t bh[2] = {Khi[rk + c0], Khi[rk + c0 + 4]};
                uint32_t bl[2] = {Klo[rk + c0], Klo[rk + c0 + 4]};
                mma_bf16(s[nb], qh[kb], bh);
                mma_bf16(s[nb], ql[kb], bh);
                mma_bf16(s[nb], qh[kb], bl);
            }
        }

        // ---- online softmax on fragments (rows qr and qr+8) ----
        float mx0 = s[0][0], mx1 = s[0][2];
        #pragma unroll
        for (int nb = 0; nb < 8; nb++) {
            mx0 = fmaxf(mx0, fmaxf(s[nb][0], s[nb][1]));
            mx1 = fmaxf(mx1, fmaxf(s[nb][2], s[nb][3]));
        }
        mx0 = fmaxf(mx0, __shfl_xor_sync(0xffffffffu, mx0, 1));
        mx0 = fmaxf(mx0, __shfl_xor_sync(0xffffffffu, mx0, 2));
        mx1 = fmaxf(mx1, __shfl_xor_sync(0xffffffffu, mx1, 1));
        mx1 = fmaxf(mx1, __shfl_xor_sync(0xffffffffu, mx1, 2));
        float mn0 = fmaxf(mrow[0], mx0);
        float mn1 = fmaxf(mrow[1], mx1);
        float al0 = ex2f(mrow[0] - mn0);
        float al1 = ex2f(mrow[1] - mn1);
        mrow[0] = mn0; mrow[1] = mn1;

        float sum0 = 0.f, sum1 = 0.f;
        #pragma unroll
        for (int nb = 0; nb < 8; nb++) {
            s[nb][0] = ex2f(s[nb][0] - mn0);
            s[nb][1] = ex2f(s[nb][1] - mn0);
            s[nb][2] = ex2f(s[nb][2] - mn1);
            s[nb][3] = ex2f(s[nb][3] - mn1);
            sum0 += s[nb][0] + s[nb][1];
            sum1 += s[nb][2] + s[nb][3];
        }
        sum0 += __shfl_xor_sync(0xffffffffu, sum0, 1);
        sum0 += __shfl_xor_sync(0xffffffffu, sum0, 2);
        sum1 += __shfl_xor_sync(0xffffffffu, sum1, 1);
        sum1 += __shfl_xor_sync(0xffffffffu, sum1, 2);
        lrow[0] = lrow[0]*al0 + sum0;
        lrow[1] = lrow[1]*al1 + sum1;

        #pragma unroll
        for (int nb = 0; nb < 8; nb++) {
            o[nb][0] *= al0; o[nb][1] *= al0;
            o[nb][2] *= al1; o[nb][3] *= al1;
        }

        // ---- pack P into A-fragments (hi + residual lo) ----
        uint32_t ph[4][4], pl[4][4];
        #pragma unroll
        for (int kb = 0; kb < 4; kb++) {
            split2(s[2*kb][0],   s[2*kb][1],   ph[kb][0], pl[kb][0]);
            split2(s[2*kb][2],   s[2*kb][3],   ph[kb][1], pl[kb][1]);
            split2(s[2*kb+1][0], s[2*kb+1][1], ph[kb][2], pl[kb][2]);
            split2(s[2*kb+1][2], s[2*kb+1][3], ph[kb][3], pl[kb][3]);
        }

        // ---- O += P V (3-pass split) ----
        #pragma unroll
        for (int kb = 0; kb < 4; kb++) {
            int c0 = kb*8 + cq;
            #pragma unroll
            for (int nb = 0; nb < 8; nb++) {
                int rv = (nb*8 + qr)*KST;
                uint32_t vh[2] = {Vhi[rv + c0], Vhi[rv + c0 + 4]};
                uint32_t vl[2] = {Vlo[rv + c0], Vlo[rv + c0 + 4]};
                mma_bf16(o[nb], ph[kb], vh);
                mma_bf16(o[nb], pl[kb], vh);
                mma_bf16(o[nb], ph[kb], vl);
            }
        }
    }

    // ---- normalize and write out [t][d] ----
    float inv0 = 1.0f / lrow[0];
    float inv1 = 1.0f / lrow[1];
    int rowa = qt*64 + warp*16 + qr;
    #pragma unroll
    for (int nb = 0; nb < 8; nb++) {
        int col = h*DH + nb*8 + 2*cq;
        *(float2*)(g_ob + (size_t)rowa*ND + col) =
            make_float2(o[nb][0]*inv0, o[nb][1]*inv0);
        *(float2*)(g_ob + (size_t)(rowa+8)*ND + col) =
            make_float2(o[nb][2]*inv1, o[nb][3]*inv1);
    }
}

// ---------------------------------------------------------------------------
// Kernel 3 (per batch): output projection + bias (round-7 validated).
// ---------------------------------------------------------------------------
__global__ __launch_bounds__(256) void out_mma_kernel(
    const float* __restrict__ W, const float* __restrict__ bias,
    float* __restrict__ Yb)
{
    __shared__ GemmSmem s;
    float acc[4][4][4];
    gemm_bf16_core(g_ob, W, ND, s, acc);

    const int lane   = threadIdx.x & 31;
    const int wid    = threadIdx.x >> 5;
    const int warp_m = (wid & 1) * 64;
    const int warp_n = (wid >> 1) * 32;

    const int ncol0 = blockIdx.y*128 + warp_n + 2*(lane & 3);
    float2 bset[4];
    #pragma unroll
    for (int ni = 0; ni < 4; ni++)
        bset[ni] = make_float2(bias[ncol0 + ni*8], bias[ncol0 + ni*8 + 1]);

    #pragma unroll
    for (int mi = 0; mi < 4; mi++) {
        #pragma unroll
        for (int half = 0; half < 2; half++) {
            int grow = blockIdx.x*128 + warp_m + mi*16 + (lane >> 2) + half*8;
            float* dst = Yb + (size_t)grow*ND + ncol0;
            #pragma unroll
            for (int ni = 0; ni < 4; ni++) {
                float2 v = make_float2(acc[mi][ni][2*half]   + bset[ni].x,
                                       acc[mi][ni][2*half+1] + bset[ni].y);
                *(float2*)(dst + ni*8) = v;
            }
        }
    }
}

// ---------------------------------------------------------------------------
extern "C" void kernel_launch(void* const* d_in, const int* in_sizes, int n_in,
                              void* d_out, int out_size)
{
    // Identify inputs by element count:
    //   x 4194304, w_qkv 3145728, w_out 1048576, b_out 1024, memory 524288
    const float *x = nullptr, *w_qkv = nullptr, *w_out = nullptr,
                *b_out = nullptr, *memory = nullptr;
    for (int i = 0; i < n_in; i++) {
        switch (in_sizes[i]) {
            case 4194304: x      = (const float*)d_in[i]; break;
            case 3145728: w_qkv  = (const float*)d_in[i]; break;
            case 1048576: w_out  = (const float*)d_in[i]; break;
            case 1024:    b_out  = (const float*)d_in[i]; break;
            case 524288:  memory = (const float*)d_in[i]; break;
            default: break;
        }
    }
    float* out = (float*)d_out;

    // Pack memory K/V once (keys [0, 512) for every head, both batches).
    pack_memory_kernel<<<NMEM*ND/256, 256>>>(memory);

    for (int b = 0; b < NB; b++) {
        const float* xb = x + (size_t)b*NT*ND;
        float*       yb = out + (size_t)b*NT*ND;
        qkv_mma_kernel<<<dim3(NT/128, 3*ND/128), 256>>>(xb, w_qkv);   // 16 x 24
        attn_mma_kernel<<<dim3(NT/64, NH), 128>>>();                  // 32 x 16
        out_mma_kernel<<<dim3(NT/128, ND/128), 256>>>(w_out, b_out, yb); // 16 x 8
    }
}

// round 10
// speedup vs baseline: 3.1969x; 1.6869x over previous
#include <cuda_runtime.h>
#include <cuda_bf16.h>
#include <cstdint>

// Problem constants
#define NB    2
#define NT    2048
#define ND    1024
#define NH    16
#define DH    64
#define NMEM  512
#define NKV   2560      // MEM + T

#define LOG2E 1.4426950408889634f

// Per-batch scratch (allocation-free __device__ globals, ~37 MB total)
__device__ float    g_q  [NH*NT*DH];     // fp32 Q, [h][t][c]          8 MB
__device__ uint32_t g_khl[NH*NKV*DH];    // packed bf16 hi|lo K        10.5 MB
__device__ uint32_t g_vhl[NH*NKV*DH];    // packed bf16 hi|lo V        10.5 MB
__device__ float    g_ob [NT*ND];        // attention out, [t][d]      8 MB

// ===========================================================================
// helpers
// ===========================================================================
__device__ __forceinline__ uint32_t smem_u32(const void* p) {
    uint32_t a;
    asm("{ .reg .u64 t; cvta.to.shared.u64 t, %1; cvt.u32.u64 %0, t; }"
        : "=r"(a) : "l"(p));
    return a;
}
__device__ __forceinline__ uint32_t pack_bf16x2(float lo, float hi) {
    __nv_bfloat162 h = __float22bfloat162_rn(make_float2(lo, hi));
    return *reinterpret_cast<uint32_t*>(&h);
}
__device__ __forceinline__ float bf16lo_to_f32(uint32_t p) {
    return __uint_as_float(p << 16);
}
__device__ __forceinline__ float bf16hi_to_f32(uint32_t p) {
    return __uint_as_float(p & 0xffff0000u);
}
__device__ __forceinline__ uint32_t bf16bits(float v) {
    __nv_bfloat16 b = __float2bfloat16(v);
    return (uint32_t)*reinterpret_cast<unsigned short*>(&b);
}
__device__ __forceinline__ uint32_t packword(float v) {
    uint32_t hb = bf16bits(v);
    float hv = __uint_as_float(hb << 16);
    uint32_t lb = bf16bits(v - hv);
    return (hb << 16) | lb;
}
__device__ __forceinline__ uint32_t hipair(uint32_t e0, uint32_t e1) {
    uint32_t r;
    asm("prmt.b32 %0,%1,%2,0x7632;" : "=r"(r) : "r"(e0), "r"(e1));
    return r;
}
__device__ __forceinline__ uint32_t lopair(uint32_t e0, uint32_t e1) {
    uint32_t r;
    asm("prmt.b32 %0,%1,%2,0x5410;" : "=r"(r) : "r"(e0), "r"(e1));
    return r;
}
__device__ __forceinline__ void split2(float x, float y,
                                       uint32_t& hi, uint32_t& lo) {
    uint32_t p = pack_bf16x2(x, y);
    lo = pack_bf16x2(x - bf16lo_to_f32(p), y - bf16hi_to_f32(p));
    hi = p;
}
__device__ __forceinline__ float ex2f(float x) {
    float r;
    asm("ex2.approx.ftz.f32 %0,%1;" : "=f"(r) : "f"(x));
    return r;
}
__device__ __forceinline__ void mma_bf16(float (&c)[4],
                                         const uint32_t (&a)[4],
                                         const uint32_t (&b)[2]) {
    asm volatile(
        "mma.sync.aligned.m16n8k16.row.col.f32.bf16.bf16.f32 "
        "{%0,%1,%2,%3}, {%4,%5,%6,%7}, {%8,%9}, {%0,%1,%2,%3};"
        : "+f"(c[0]), "+f"(c[1]), "+f"(c[2]), "+f"(c[3])
        : "r"(a[0]), "r"(a[1]), "r"(a[2]), "r"(a[3]),
          "r"(b[0]), "r"(b[1]));
}
__device__ __forceinline__ void ldsm_x4(uint32_t& r0, uint32_t& r1,
                                        uint32_t& r2, uint32_t& r3,
                                        uint32_t addr) {
    asm volatile(
        "ldmatrix.sync.aligned.m8n8.x4.shared.b16 {%0,%1,%2,%3}, [%4];"
        : "=r"(r0), "=r"(r1), "=r"(r2), "=r"(r3) : "r"(addr));
}

// ===========================================================================
// Templated split-bf16 GEMM core with ldmatrix fragment loads.
// Tile (MI*32) x (NI*32) of A[M,K]*B[N,K]^T; 256 thr, 8 warps 2(m)x4(n).
// ===========================================================================
#define SROW 20

template<int MI, int NI>
struct GemmSmemT {
    uint32_t Ahi[MI*32*SROW];
    uint32_t Alo[MI*32*SROW];
    uint32_t Bhi[NI*32*SROW];
    uint32_t Blo[NI*32*SROW];
};

template<int MI, int NI>
__device__ __forceinline__ void gemm_core_t(
    const float* __restrict__ A, const float* __restrict__ B, int K,
    GemmSmemT<MI,NI>& s, float (&acc)[MI][NI][4])
{
    const int tid    = threadIdx.x;
    const int lane   = tid & 31;
    const int wid    = tid >> 5;
    const int warp_m = (wid & 1) * (MI*16);
    const int warp_n = (wid >> 1) * (NI*8);

    #pragma unroll
    for (int mi = 0; mi < MI; mi++)
        #pragma unroll
        for (int ni = 0; ni < NI; ni++)
            #pragma unroll
            for (int r = 0; r < 4; r++) acc[mi][ni][r] = 0.f;

    const int lf4   = tid & 7;
    const int rbase = tid >> 3;
    const float* Ap = A + (size_t)(blockIdx.x*(MI*32) + rbase)*K + lf4*4;
    const float* Bp = B + (size_t)(blockIdx.y*(NI*32) + rbase)*K + lf4*4;

    const uint32_t uAhi = smem_u32(s.Ahi), uAlo = smem_u32(s.Alo);
    const uint32_t uBhi = smem_u32(s.Bhi), uBlo = smem_u32(s.Blo);
    // ldmatrix per-lane offsets
    const int a_row = (lane & 7) + ((lane >> 3) & 1) * 8;
    const int a_kp  = (lane >> 4) * 4;
    const int b_row = (lane & 7) + ((lane >> 4) & 1) * 8;
    const int b_kp  = ((lane >> 3) & 1) * 4;

    const int nchunks = K / 32;
    for (int c = 0; c < nchunks; c++) {
        __syncthreads();
        #pragma unroll
        for (int i = 0; i < MI; i++) {
            int so = (i*32 + rbase)*SROW + 2*lf4;
            float4 va = *(const float4*)(Ap + (size_t)(i*32)*K + c*32);
            uint32_t h0, h1, l0, l1;
            split2(va.x, va.y, h0, l0);
            split2(va.z, va.w, h1, l1);
            *(uint2*)&s.Ahi[so] = make_uint2(h0, h1);
            *(uint2*)&s.Alo[so] = make_uint2(l0, l1);
        }
        #pragma unroll
        for (int i = 0; i < NI; i++) {
            int so = (i*32 + rbase)*SROW + 2*lf4;
            float4 vb = *(const float4*)(Bp + (size_t)(i*32)*K + c*32);
            uint32_t h0, h1, l0, l1;
            split2(vb.x, vb.y, h0, l0);
            split2(vb.z, vb.w, h1, l1);
            *(uint2*)&s.Bhi[so] = make_uint2(h0, h1);
            *(uint2*)&s.Blo[so] = make_uint2(l0, l1);
        }
        __syncthreads();

        #pragma unroll
        for (int ks = 0; ks < 2; ks++) {
            uint32_t ah[MI][4], al[MI][4], bh[NI][2], bl[NI][2];
            #pragma unroll
            for (int mi = 0; mi < MI; mi++) {
                uint32_t off =
                    ((warp_m + mi*16 + a_row)*SROW + ks*8 + a_kp) * 4u;
                ldsm_x4(ah[mi][0], ah[mi][1], ah[mi][2], ah[mi][3],
                        uAhi + off);
                ldsm_x4(al[mi][0], al[mi][1], al[mi][2], al[mi][3],
                        uAlo + off);
            }
            #pragma unroll
            for (int p = 0; p < NI/2; p++) {
                uint32_t off =
                    ((warp_n + p*16 + b_row)*SROW + ks*8 + b_kp) * 4u;
                ldsm_x4(bh[2*p][0], bh[2*p][1], bh[2*p+1][0], bh[2*p+1][1],
                        uBhi + off);
                ldsm_x4(bl[2*p][0], bl[2*p][1], bl[2*p+1][0], bl[2*p+1][1],
                        uBlo + off);
            }
            #pragma unroll
            for (int ni = 0; ni < NI; ni++)
                #pragma unroll
                for (int mi = 0; mi < MI; mi++)
                    mma_bf16(acc[mi][ni], ah[mi], bh[ni]);
            #pragma unroll
            for (int ni = 0; ni < NI; ni++)
                #pragma unroll
                for (int mi = 0; mi < MI; mi++)
                    mma_bf16(acc[mi][ni], al[mi], bh[ni]);
            #pragma unroll
            for (int ni = 0; ni < NI; ni++)
                #pragma unroll
                for (int mi = 0; mi < MI; mi++)
                    mma_bf16(acc[mi][ni], ah[mi], bl[ni]);
        }
    }
}

// ---------------------------------------------------------------------------
// Kernel 0 (once): pack `memory` into K/V hi|lo buffers, keys [0, 512).
// ---------------------------------------------------------------------------
__global__ void pack_memory_kernel(const float* __restrict__ mem)
{
    int id = blockIdx.x*256 + threadIdx.x;
    int key = id >> 10;
    int dg  = id & 1023;
    int h   = dg >> 6;
    int c   = dg & 63;
    uint32_t w = packword(mem[id]);
    size_t dst = ((size_t)h*NKV + key)*DH + c;
    g_khl[dst] = w;
    g_vhl[dst] = w;
}

// ---------------------------------------------------------------------------
// Kernel 1 (per batch): QKV projection (128x128 tiles); Q fp32, K/V packed.
// Grid (16, 24), 256 threads.
// ---------------------------------------------------------------------------
__global__ __launch_bounds__(256) void qkv_mma_kernel(
    const float* __restrict__ X, const float* __restrict__ W)
{
    __shared__ GemmSmemT<4,4> s;
    float acc[4][4][4];
    gemm_core_t<4,4>(X, W, ND, s, acc);

    const int lane   = threadIdx.x & 31;
    const int wid    = threadIdx.x >> 5;
    const int warp_m = (wid & 1) * 64;
    const int warp_n = (wid >> 1) * 32;

    const int bn    = blockIdx.y;
    const int sec   = bn >> 3;                          // 0=q,1=k,2=v
    const int h     = (((bn & 7)*128) + warp_n) >> 6;
    const int cbase = (warp_n & 32) + 2*(lane & 3);

    if (sec == 0) {
        #pragma unroll
        for (int mi = 0; mi < 4; mi++)
            #pragma unroll
            for (int half = 0; half < 2; half++) {
                int t = blockIdx.x*128 + warp_m + mi*16 + (lane >> 2) + half*8;
                float* dst = g_q + ((size_t)h*NT + t)*DH + cbase;
                #pragma unroll
                for (int ni = 0; ni < 4; ni++)
                    *(float2*)(dst + ni*8) =
                        make_float2(acc[mi][ni][2*half], acc[mi][ni][2*half+1]);
            }
    } else {
        uint32_t* gb = (sec == 1) ? g_khl : g_vhl;
        #pragma unroll
        for (int mi = 0; mi < 4; mi++)
            #pragma unroll
            for (int half = 0; half < 2; half++) {
                int t = blockIdx.x*128 + warp_m + mi*16 + (lane >> 2) + half*8;
                uint32_t* dst = gb + ((size_t)h*NKV + NMEM + t)*DH + cbase;
                #pragma unroll
                for (int ni = 0; ni < 4; ni++)
                    *(uint2*)(dst + ni*8) =
                        make_uint2(packword(acc[mi][ni][2*half]),
                                   packword(acc[mi][ni][2*half+1]));
            }
    }
}

// ---------------------------------------------------------------------------
// Kernel 2 (per batch): flash attention, split-bf16 mma + ldmatrix feeds.
// Grid (T/64, H) = (32, 16), 128 threads (4 warps x 16 q-rows).
// ---------------------------------------------------------------------------
#define KST 36

__global__ __launch_bounds__(128, 3) void attn_mma_kernel()
{
    __shared__ uint32_t Khi[64*KST], Klo[64*KST];   // [key][d-pair]
    __shared__ uint32_t Vhi[64*KST], Vlo[64*KST];   // [d][key-pair]

    const int tid  = threadIdx.x;
    const int lane = tid & 31;
    const int warp = tid >> 5;
    const int qt   = blockIdx.x;
    const int h    = blockIdx.y;
    const int qr   = lane >> 2;
    const int cq   = lane & 3;

    const uint32_t uKhi = smem_u32(Khi), uKlo = smem_u32(Klo);
    const uint32_t uVhi = smem_u32(Vhi), uVlo = smem_u32(Vlo);
    const int b_row = (lane & 7) + ((lane >> 4) & 1) * 8;
    const int b_kp  = ((lane >> 3) & 1) * 4;

    // ---- stage Q (scaled, split) into Khi/Klo, then load A-fragments ----
    {
        const float qsc = 0.125f * LOG2E;
        int row = tid >> 1;
        int d0  = (tid & 1) * 32;
        const float* src = g_q + ((size_t)h*NT + qt*64 + row)*DH + d0;
        #pragma unroll
        for (int i = 0; i < 8; i++) {
            float4 v = *(const float4*)(src + i*4);
            uint32_t h0, h1, l0, l1;
            split2(v.x*qsc, v.y*qsc, h0, l0);
            split2(v.z*qsc, v.w*qsc, h1, l1);
            int so = row*KST + d0/2 + 2*i;
            *(uint2*)&Khi[so] = make_uint2(h0, h1);
            *(uint2*)&Klo[so] = make_uint2(l0, l1);
        }
    }
    __syncthreads();

    uint32_t qh[4][4], ql[4][4];
    {
        const int a_row = (lane & 7) + ((lane >> 3) & 1) * 8;
        const int a_kp  = (lane >> 4) * 4;
        #pragma unroll
        for (int kb = 0; kb < 4; kb++) {
            uint32_t off = ((warp*16 + a_row)*KST + kb*8 + a_kp) * 4u;
            ldsm_x4(qh[kb][0], qh[kb][1], qh[kb][2], qh[kb][3], uKhi + off);
            ldsm_x4(ql[kb][0], ql[kb][1], ql[kb][2], ql[kb][3], uKlo + off);
        }
    }

    float o[8][4];
    #pragma unroll
    for (int nb = 0; nb < 8; nb++)
        #pragma unroll
        for (int r = 0; r < 4; r++) o[nb][r] = 0.f;
    float mrow[2] = {-1e30f, -1e30f};
    float lrow[2] = {0.f, 0.f};

    const uint32_t* kbase = g_khl + (size_t)h*NKV*DH;
    const uint32_t* vbase = g_vhl + (size_t)h*NKV*DH;

    for (int kt = 0; kt < NKV/64; kt++) {
        __syncthreads();
        // ---- convert K tile: [key][d] words -> hi/lo bf16x2 d-pairs ----
        {
            const uint32_t* src = kbase + (size_t)(kt*64)*DH + 4*(tid & 15);
            int dp = 2*(tid & 15);
            #pragma unroll
            for (int j = 0; j < 8; j++) {
                int key = (tid >> 4) + j*8;
                uint4 e = *(const uint4*)(src + key*DH);
                int so = key*KST + dp;
                *(uint2*)&Khi[so] = make_uint2(hipair(e.x, e.y), hipair(e.z, e.w));
                *(uint2*)&Klo[so] = make_uint2(lopair(e.x, e.y), lopair(e.z, e.w));
            }
        }
        // ---- convert V tile transposed: [d][key-pair] ----
        {
            const uint32_t* src = vbase + (size_t)(kt*64)*DH + 4*(tid & 15);
            int d = 4*(tid & 15);
            #pragma unroll
            for (int j = 0; j < 4; j++) {
                int kp = (tid >> 4) + j*8;
                uint4 a = *(const uint4*)(src + (2*kp)*DH);
                uint4 b = *(const uint4*)(src + (2*kp + 1)*DH);
                Vhi[(d+0)*KST + kp] = hipair(a.x, b.x);
                Vhi[(d+1)*KST + kp] = hipair(a.y, b.y);
                Vhi[(d+2)*KST + kp] = hipair(a.z, b.z);
                Vhi[(d+3)*KST + kp] = hipair(a.w, b.w);
                Vlo[(d+0)*KST + kp] = lopair(a.x, b.x);
                Vlo[(d+1)*KST + kp] = lopair(a.y, b.y);
                Vlo[(d+2)*KST + kp] = lopair(a.z, b.z);
                Vlo[(d+3)*KST + kp] = lopair(a.w, b.w);
            }
        }
        __syncthreads();

        // ---- S = Q K^T (3-pass split, ldmatrix K-frags) ----
        float s[8][4];
        #pragma unroll
        for (int nb = 0; nb < 8; nb++)
            #pragma unroll
            for (int r = 0; r < 4; r++) s[nb][r] = 0.f;
        #pragma unroll
        for (int kb = 0; kb < 4; kb++) {
            #pragma unroll
            for (int p = 0; p < 4; p++) {
                uint32_t off = ((p*16 + b_row)*KST + kb*8 + b_kp) * 4u;
                uint32_t bh0[2], bh1[2], bl0[2], bl1[2];
                ldsm_x4(bh0[0], bh0[1], bh1[0], bh1[1], uKhi + off);
                ldsm_x4(bl0[0], bl0[1], bl1[0], bl1[1], uKlo + off);
                mma_bf16(s[2*p],   qh[kb], bh0);
                mma_bf16(s[2*p],   ql[kb], bh0);
                mma_bf16(s[2*p],   qh[kb], bl0);
                mma_bf16(s[2*p+1], qh[kb], bh1);
                mma_bf16(s[2*p+1], ql[kb], bh1);
                mma_bf16(s[2*p+1], qh[kb], bl1);
            }
        }

        // ---- online softmax on fragments (rows qr and qr+8) ----
        float mx0 = s[0][0], mx1 = s[0][2];
        #pragma unroll
        for (int nb = 0; nb < 8; nb++) {
            mx0 = fmaxf(mx0, fmaxf(s[nb][0], s[nb][1]));
            mx1 = fmaxf(mx1, fmaxf(s[nb][2], s[nb][3]));
        }
        mx0 = fmaxf(mx0, __shfl_xor_sync(0xffffffffu, mx0, 1));
        mx0 = fmaxf(mx0, __shfl_xor_sync(0xffffffffu, mx0, 2));
        mx1 = fmaxf(mx1, __shfl_xor_sync(0xffffffffu, mx1, 1));
        mx1 = fmaxf(mx1, __shfl_xor_sync(0xffffffffu, mx1, 2));
        float mn0 = fmaxf(mrow[0], mx0);
        float mn1 = fmaxf(mrow[1], mx1);
        float al0 = ex2f(mrow[0] - mn0);
        float al1 = ex2f(mrow[1] - mn1);
        mrow[0] = mn0; mrow[1] = mn1;

        float sum0 = 0.f, sum1 = 0.f;
        #pragma unroll
        for (int nb = 0; nb < 8; nb++) {
            s[nb][0] = ex2f(s[nb][0] - mn0);
            s[nb][1] = ex2f(s[nb][1] - mn0);
            s[nb][2] = ex2f(s[nb][2] - mn1);
            s[nb][3] = ex2f(s[nb][3] - mn1);
            sum0 += s[nb][0] + s[nb][1];
            sum1 += s[nb][2] + s[nb][3];
        }
        sum0 += __shfl_xor_sync(0xffffffffu, sum0, 1);
        sum0 += __shfl_xor_sync(0xffffffffu, sum0, 2);
        sum1 += __shfl_xor_sync(0xffffffffu, sum1, 1);
        sum1 += __shfl_xor_sync(0xffffffffu, sum1, 2);
        lrow[0] = lrow[0]*al0 + sum0;
        lrow[1] = lrow[1]*al1 + sum1;

        #pragma unroll
        for (int nb = 0; nb < 8; nb++) {
            o[nb][0] *= al0; o[nb][1] *= al0;
            o[nb][2] *= al1; o[nb][3] *= al1;
        }

        // ---- O += P V: pack P per-kb, fused (3-pass split, ldmatrix V) ----
        #pragma unroll
        for (int kb = 0; kb < 4; kb++) {
            uint32_t ph[4], pl[4];
            split2(s[2*kb][0],   s[2*kb][1],   ph[0], pl[0]);
            split2(s[2*kb][2],   s[2*kb][3],   ph[1], pl[1]);
            split2(s[2*kb+1][0], s[2*kb+1][1], ph[2], pl[2]);
            split2(s[2*kb+1][2], s[2*kb+1][3], ph[3], pl[3]);
            #pragma unroll
            for (int p = 0; p < 4; p++) {
                uint32_t off = ((p*16 + b_row)*KST + kb*8 + b_kp) * 4u;
                uint32_t vh0[2], vh1[2], vl0[2], vl1[2];
                ldsm_x4(vh0[0], vh0[1], vh1[0], vh1[1], uVhi + off);
                ldsm_x4(vl0[0], vl0[1], vl1[0], vl1[1], uVlo + off);
                mma_bf16(o[2*p],   ph, vh0);
                mma_bf16(o[2*p],   pl, vh0);
                mma_bf16(o[2*p],   ph, vl0);
                mma_bf16(o[2*p+1], ph, vh1);
                mma_bf16(o[2*p+1], pl, vh1);
                mma_bf16(o[2*p+1], ph, vl1);
            }
        }
    }

    // ---- normalize and write out [t][d] ----
    float inv0 = 1.0f / lrow[0];
    float inv1 = 1.0f / lrow[1];
    int rowa = qt*64 + warp*16 + qr;
    #pragma unroll
    for (int nb = 0; nb < 8; nb++) {
        int col = h*DH + nb*8 + 2*cq;
        *(float2*)(g_ob + (size_t)rowa*ND + col) =
            make_float2(o[nb][0]*inv0, o[nb][1]*inv0);
        *(float2*)(g_ob + (size_t)(rowa+8)*ND + col) =
            make_float2(o[nb][2]*inv1, o[nb][3]*inv1);
    }
}

// ---------------------------------------------------------------------------
// Kernel 3 (per batch): output projection + bias, 64x128 tiles.
// Grid (NT/64, ND/128) = (32, 8), 256 threads.
// ---------------------------------------------------------------------------
__global__ __launch_bounds__(256) void out_mma_kernel(
    const float* __restrict__ W, const float* __restrict__ bias,
    float* __restrict__ Yb)
{
    __shared__ GemmSmemT<2,4> s;
    float acc[2][4][4];
    gemm_core_t<2,4>(g_ob, W, ND, s, acc);

    const int lane   = threadIdx.x & 31;
    const int wid    = threadIdx.x >> 5;
    const int warp_m = (wid & 1) * 32;
    const int warp_n = (wid >> 1) * 32;

    const int ncol0 = blockIdx.y*128 + warp_n + 2*(lane & 3);
    float2 bset[4];
    #pragma unroll
    for (int ni = 0; ni < 4; ni++)
        bset[ni] = make_float2(bias[ncol0 + ni*8], bias[ncol0 + ni*8 + 1]);

    #pragma unroll
    for (int mi = 0; mi < 2; mi++) {
        #pragma unroll
        for (int half = 0; half < 2; half++) {
            int grow = blockIdx.x*64 + warp_m + mi*16 + (lane >> 2) + half*8;
            float* dst = Yb + (size_t)grow*ND + ncol0;
            #pragma unroll
            for (int ni = 0; ni < 4; ni++) {
                float2 v = make_float2(acc[mi][ni][2*half]   + bset[ni].x,
                                       acc[mi][ni][2*half+1] + bset[ni].y);
                *(float2*)(dst + ni*8) = v;
            }
        }
    }
}

// ---------------------------------------------------------------------------
extern "C" void kernel_launch(void* const* d_in, const int* in_sizes, int n_in,
                              void* d_out, int out_size)
{
    // Identify inputs by element count:
    //   x 4194304, w_qkv 3145728, w_out 1048576, b_out 1024, memory 524288
    const float *x = nullptr, *w_qkv = nullptr, *w_out = nullptr,
                *b_out = nullptr, *memory = nullptr;
    for (int i = 0; i < n_in; i++) {
        switch (in_sizes[i]) {
            case 4194304: x      = (const float*)d_in[i]; break;
            case 3145728: w_qkv  = (const float*)d_in[i]; break;
            case 1048576: w_out  = (const float*)d_in[i]; break;
            case 1024:    b_out  = (const float*)d_in[i]; break;
            case 524288:  memory = (const float*)d_in[i]; break;
            default: break;
        }
    }
    float* out = (float*)d_out;

    // Pack memory K/V once (keys [0, 512) for every head, both batches).
    pack_memory_kernel<<<NMEM*ND/256, 256>>>(memory);

    for (int b = 0; b < NB; b++) {
        const float* xb = x + (size_t)b*NT*ND;
        float*       yb = out + (size_t)b*NT*ND;
        qkv_mma_kernel<<<dim3(NT/128, 3*ND/128), 256>>>(xb, w_qkv);      // 16 x 24
        attn_mma_kernel<<<dim3(NT/64, NH), 128>>>();                     // 32 x 16
        out_mma_kernel<<<dim3(NT/64, ND/128), 256>>>(w_out, b_out, yb);  // 32 x 8
    }
}

// round 11
// speedup vs baseline: 3.8194x; 1.1947x over previous
#include <cuda_runtime.h>
#include <cuda_bf16.h>
#include <cstdint>

// Problem constants
#define NB    2
#define NT    2048
#define ND    1024
#define NH    16
#define DH    64
#define DHP   32        // d-pairs per head
#define NMEM  512
#define NKV   2560      // MEM + T

#define LOG2E 1.4426950408889634f

// Per-batch scratch (allocation-free __device__ globals, ~37 MB total)
__device__ float    g_q  [NH*NT*DH];      // fp32 Q, [h][t][c]            8 MB
__device__ uint32_t g_khi[NH*NKV*DHP];    // K hi bf16x2 pairs [h][key][dp] 5.24 MB
__device__ uint32_t g_klo[NH*NKV*DHP];    // K lo residual pairs
__device__ uint32_t g_vhi[NH*NKV*DHP];    // V hi pairs
__device__ uint32_t g_vlo[NH*NKV*DHP];    // V lo pairs
__device__ float    g_ob [NT*ND];         // attention out, [t][d]        8 MB

// ===========================================================================
// helpers
// ===========================================================================
__device__ __forceinline__ uint32_t smem_u32(const void* p) {
    uint32_t a;
    asm("{ .reg .u64 t; cvta.to.shared.u64 t, %1; cvt.u32.u64 %0, t; }"
        : "=r"(a) : "l"(p));
    return a;
}
__device__ __forceinline__ uint32_t pack_bf16x2(float lo, float hi) {
    __nv_bfloat162 h = __float22bfloat162_rn(make_float2(lo, hi));
    return *reinterpret_cast<uint32_t*>(&h);
}
__device__ __forceinline__ float bf16lo_to_f32(uint32_t p) {
    return __uint_as_float(p << 16);
}
__device__ __forceinline__ float bf16hi_to_f32(uint32_t p) {
    return __uint_as_float(p & 0xffff0000u);
}
__device__ __forceinline__ void split2(float x, float y,
                                       uint32_t& hi, uint32_t& lo) {
    uint32_t p = pack_bf16x2(x, y);
    lo = pack_bf16x2(x - bf16lo_to_f32(p), y - bf16hi_to_f32(p));
    hi = p;
}
__device__ __forceinline__ float ex2f(float x) {
    float r;
    asm("ex2.approx.ftz.f32 %0,%1;" : "=f"(r) : "f"(x));
    return r;
}
__device__ __forceinline__ void mma_bf16(float (&c)[4],
                                         const uint32_t (&a)[4],
                                         const uint32_t (&b)[2]) {
    asm volatile(
        "mma.sync.aligned.m16n8k16.row.col.f32.bf16.bf16.f32 "
        "{%0,%1,%2,%3}, {%4,%5,%6,%7}, {%8,%9}, {%0,%1,%2,%3};"
        : "+f"(c[0]), "+f"(c[1]), "+f"(c[2]), "+f"(c[3])
        : "r"(a[0]), "r"(a[1]), "r"(a[2]), "r"(a[3]),
          "r"(b[0]), "r"(b[1]));
}
__device__ __forceinline__ void ldsm_x4(uint32_t& r0, uint32_t& r1,
                                        uint32_t& r2, uint32_t& r3,
                                        uint32_t addr) {
    asm volatile(
        "ldmatrix.sync.aligned.m8n8.x4.shared.b16 {%0,%1,%2,%3}, [%4];"
        : "=r"(r0), "=r"(r1), "=r"(r2), "=r"(r3) : "r"(addr));
}
__device__ __forceinline__ void ldsm_x4_t(uint32_t& r0, uint32_t& r1,
                                          uint32_t& r2, uint32_t& r3,
                                          uint32_t addr) {
    asm volatile(
        "ldmatrix.sync.aligned.m8n8.x4.trans.shared.b16 {%0,%1,%2,%3}, [%4];"
        : "=r"(r0), "=r"(r1), "=r"(r2), "=r"(r3) : "r"(addr));
}
#define CP_ASYNC16(dst_u32, src_ptr) \
    asm volatile("cp.async.cg.shared.global [%0], [%1], 16;" \
                 :: "r"(dst_u32), "l"(src_ptr))
#define CP_COMMIT()  asm volatile("cp.async.commit_group;" ::: "memory")
#define CP_WAIT0()   asm volatile("cp.async.wait_group 0;" ::: "memory")

// ===========================================================================
// Templated split-bf16 GEMM core with ldmatrix fragment loads (round 10).
// ===========================================================================
#define SROW 20

template<int MI, int NI>
struct GemmSmemT {
    uint32_t Ahi[MI*32*SROW];
    uint32_t Alo[MI*32*SROW];
    uint32_t Bhi[NI*32*SROW];
    uint32_t Blo[NI*32*SROW];
};

template<int MI, int NI>
__device__ __forceinline__ void gemm_core_t(
    const float* __restrict__ A, const float* __restrict__ B, int K,
    GemmSmemT<MI,NI>& s, float (&acc)[MI][NI][4])
{
    const int tid    = threadIdx.x;
    const int lane   = tid & 31;
    const int wid    = tid >> 5;
    const int warp_m = (wid & 1) * (MI*16);
    const int warp_n = (wid >> 1) * (NI*8);

    #pragma unroll
    for (int mi = 0; mi < MI; mi++)
        #pragma unroll
        for (int ni = 0; ni < NI; ni++)
            #pragma unroll
            for (int r = 0; r < 4; r++) acc[mi][ni][r] = 0.f;

    const int lf4   = tid & 7;
    const int rbase = tid >> 3;
    const float* Ap = A + (size_t)(blockIdx.x*(MI*32) + rbase)*K + lf4*4;
    const float* Bp = B + (size_t)(blockIdx.y*(NI*32) + rbase)*K + lf4*4;

    const uint32_t uAhi = smem_u32(s.Ahi), uAlo = smem_u32(s.Alo);
    const uint32_t uBhi = smem_u32(s.Bhi), uBlo = smem_u32(s.Blo);
    const int a_row = (lane & 7) + ((lane >> 3) & 1) * 8;
    const int a_kp  = (lane >> 4) * 4;
    const int b_row = (lane & 7) + ((lane >> 4) & 1) * 8;
    const int b_kp  = ((lane >> 3) & 1) * 4;

    const int nchunks = K / 32;
    for (int c = 0; c < nchunks; c++) {
        __syncthreads();
        #pragma unroll
        for (int i = 0; i < MI; i++) {
            int so = (i*32 + rbase)*SROW + 2*lf4;
            float4 va = *(const float4*)(Ap + (size_t)(i*32)*K + c*32);
            uint32_t h0, h1, l0, l1;
            split2(va.x, va.y, h0, l0);
            split2(va.z, va.w, h1, l1);
            *(uint2*)&s.Ahi[so] = make_uint2(h0, h1);
            *(uint2*)&s.Alo[so] = make_uint2(l0, l1);
        }
        #pragma unroll
        for (int i = 0; i < NI; i++) {
            int so = (i*32 + rbase)*SROW + 2*lf4;
            float4 vb = *(const float4*)(Bp + (size_t)(i*32)*K + c*32);
            uint32_t h0, h1, l0, l1;
            split2(vb.x, vb.y, h0, l0);
            split2(vb.z, vb.w, h1, l1);
            *(uint2*)&s.Bhi[so] = make_uint2(h0, h1);
            *(uint2*)&s.Blo[so] = make_uint2(l0, l1);
        }
        __syncthreads();

        #pragma unroll
        for (int ks = 0; ks < 2; ks++) {
            uint32_t ah[MI][4], al[MI][4], bh[NI][2], bl[NI][2];
            #pragma unroll
            for (int mi = 0; mi < MI; mi++) {
                uint32_t off =
                    ((warp_m + mi*16 + a_row)*SROW + ks*8 + a_kp) * 4u;
                ldsm_x4(ah[mi][0], ah[mi][1], ah[mi][2], ah[mi][3],
                        uAhi + off);
                ldsm_x4(al[mi][0], al[mi][1], al[mi][2], al[mi][3],
                        uAlo + off);
            }
            #pragma unroll
            for (int p = 0; p < NI/2; p++) {
                uint32_t off =
                    ((warp_n + p*16 + b_row)*SROW + ks*8 + b_kp) * 4u;
                ldsm_x4(bh[2*p][0], bh[2*p][1], bh[2*p+1][0], bh[2*p+1][1],
                        uBhi + off);
                ldsm_x4(bl[2*p][0], bl[2*p][1], bl[2*p+1][0], bl[2*p+1][1],
                        uBlo + off);
            }
            #pragma unroll
            for (int ni = 0; ni < NI; ni++)
                #pragma unroll
                for (int mi = 0; mi < MI; mi++)
                    mma_bf16(acc[mi][ni], ah[mi], bh[ni]);
            #pragma unroll
            for (int ni = 0; ni < NI; ni++)
                #pragma unroll
                for (int mi = 0; mi < MI; mi++)
                    mma_bf16(acc[mi][ni], al[mi], bh[ni]);
            #pragma unroll
            for (int ni = 0; ni < NI; ni++)
                #pragma unroll
                for (int mi = 0; mi < MI; mi++)
                    mma_bf16(acc[mi][ni], ah[mi], bl[ni]);
        }
    }
}

// ---------------------------------------------------------------------------
// Kernel 0 (once): pack `memory` into split-pair K/V buffers, keys [0, 512).
// One thread per d-pair: 262144 threads.
// ---------------------------------------------------------------------------
__global__ void pack_memory_kernel(const float* __restrict__ mem)
{
    int id  = blockIdx.x*256 + threadIdx.x;   // 0 .. NMEM*ND/2-1
    int key = id >> 9;                        // / (ND/2)
    int wi  = id & 511;
    int h   = wi >> 5;
    int pr  = wi & 31;
    const float* p = mem + (size_t)key*ND + h*DH + 2*pr;
    uint32_t hi, lo;
    split2(p[0], p[1], hi, lo);
    size_t dst = ((size_t)h*NKV + key)*DHP + pr;
    g_khi[dst] = hi; g_klo[dst] = lo;
    g_vhi[dst] = hi; g_vlo[dst] = lo;
}

// ---------------------------------------------------------------------------
// Kernel 1 (per batch): QKV projection; Q fp32 scatter, K/V split pairs.
// Grid (16, 24), 256 threads.
// ---------------------------------------------------------------------------
__global__ __launch_bounds__(256) void qkv_mma_kernel(
    const float* __restrict__ X, const float* __restrict__ W)
{
    __shared__ GemmSmemT<4,4> s;
    float acc[4][4][4];
    gemm_core_t<4,4>(X, W, ND, s, acc);

    const int lane   = threadIdx.x & 31;
    const int wid    = threadIdx.x >> 5;
    const int warp_m = (wid & 1) * 64;
    const int warp_n = (wid >> 1) * 32;

    const int bn  = blockIdx.y;
    const int sec = bn >> 3;                          // 0=q,1=k,2=v
    const int h   = (((bn & 7)*128) + warp_n) >> 6;

    if (sec == 0) {
        const int cbase = (warp_n & 32) + 2*(lane & 3);
        #pragma unroll
        for (int mi = 0; mi < 4; mi++)
            #pragma unroll
            for (int half = 0; half < 2; half++) {
                int t = blockIdx.x*128 + warp_m + mi*16 + (lane >> 2) + half*8;
                float* dst = g_q + ((size_t)h*NT + t)*DH + cbase;
                #pragma unroll
                for (int ni = 0; ni < 4; ni++)
                    *(float2*)(dst + ni*8) =
                        make_float2(acc[mi][ni][2*half], acc[mi][ni][2*half+1]);
            }
    } else {
        uint32_t* ghi = (sec == 1) ? g_khi : g_vhi;
        uint32_t* glo = (sec == 1) ? g_klo : g_vlo;
        const int prb = ((warp_n & 32) >> 1) + (lane & 3);
        #pragma unroll
        for (int mi = 0; mi < 4; mi++)
            #pragma unroll
            for (int half = 0; half < 2; half++) {
                int t = blockIdx.x*128 + warp_m + mi*16 + (lane >> 2) + half*8;
                size_t off = ((size_t)h*NKV + NMEM + t)*DHP + prb;
                #pragma unroll
                for (int ni = 0; ni < 4; ni++) {
                    uint32_t hi, lo;
                    split2(acc[mi][ni][2*half], acc[mi][ni][2*half+1], hi, lo);
                    ghi[off + ni*4] = hi;
                    glo[off + ni*4] = lo;
                }
            }
    }
}

// ---------------------------------------------------------------------------
// Kernel 2 (per batch): flash attention; pure-copy cp.async double-buffered
// staging + ldmatrix(.trans for V) feeding split-bf16 mma.
// Grid (T/64, H) = (32, 16), 128 threads (4 warps x 16 q-rows).
// ---------------------------------------------------------------------------
#define KST   36
#define STG   (64*KST)                    // uint32 per array per stage
#define ATTN_SMEM_BYTES (2*4*STG*4)       // 73728 B

__global__ __launch_bounds__(128, 3) void attn_mma_kernel()
{
    extern __shared__ uint32_t sb[];
    const int tid  = threadIdx.x;
    const int lane = tid & 31;
    const int warp = tid >> 5;
    const int qt   = blockIdx.x;
    const int h    = blockIdx.y;
    const int qr   = lane >> 2;
    const int cq   = lane & 3;
    const uint32_t sbu = smem_u32(sb);

    const uint32_t* gk[4] = {
        g_khi + (size_t)h*NKV*DHP, g_klo + (size_t)h*NKV*DHP,
        g_vhi + (size_t)h*NKV*DHP, g_vlo + (size_t)h*NKV*DHP };

    // copy one kt tile (4 arrays x 64 rows x 32 uint32) into stage st
    auto issue_copy = [&](int st, int kt) {
        uint32_t dbase = sbu + (uint32_t)(st*4*STG)*4u;
        #pragma unroll
        for (int a = 0; a < 4; a++) {
            const uint32_t* g = gk[a] + (size_t)(kt*64)*DHP;
            #pragma unroll
            for (int j = 0; j < 4; j++) {
                int seg = tid + j*128;            // 0..511
                int row = seg >> 3;
                int c4  = (seg & 7) * 4;
                uint32_t d = dbase + (uint32_t)(a*STG + row*KST + c4)*4u;
                CP_ASYNC16(d, g + row*DHP + c4);
            }
        }
        CP_COMMIT();
    };

    // 1) prefetch kt=0 into stage 0
    issue_copy(0, 0);

    // 2) stage Q (scaled, split) into stage-1 region (khi/klo slots)
    {
        uint32_t* qhi = sb + 4*STG;        // stage1 array0
        uint32_t* qlo = qhi + STG;         // stage1 array1
        const float qsc = 0.125f * LOG2E;
        int row = tid >> 1;
        int d0  = (tid & 1) * 32;
        const float* src = g_q + ((size_t)h*NT + qt*64 + row)*DH + d0;
        #pragma unroll
        for (int i = 0; i < 8; i++) {
            float4 v = *(const float4*)(src + i*4);
            uint32_t h0, h1, l0, l1;
            split2(v.x*qsc, v.y*qsc, h0, l0);
            split2(v.z*qsc, v.w*qsc, h1, l1);
            int so = row*KST + d0/2 + 2*i;
            *(uint2*)&qhi[so] = make_uint2(h0, h1);
            *(uint2*)&qlo[so] = make_uint2(l0, l1);
        }
    }
    __syncwarp();   // each warp stages exactly its own 16 rows

    // 3) Q a-fragments
    uint32_t qh[4][4], ql[4][4];
    {
        const int a_row = (lane & 7) + ((lane >> 3) & 1) * 8;
        const int a_kp  = (lane >> 4) * 4;
        uint32_t uQhi = sbu + (uint32_t)(4*STG)*4u;
        uint32_t uQlo = uQhi + STG*4u;
        #pragma unroll
        for (int kb = 0; kb < 4; kb++) {
            uint32_t off = ((warp*16 + a_row)*KST + kb*8 + a_kp) * 4u;
            ldsm_x4(qh[kb][0], qh[kb][1], qh[kb][2], qh[kb][3], uQhi + off);
            ldsm_x4(ql[kb][0], ql[kb][1], ql[kb][2], ql[kb][3], uQlo + off);
        }
    }

    float o[8][4];
    #pragma unroll
    for (int nb = 0; nb < 8; nb++)
        #pragma unroll
        for (int r = 0; r < 4; r++) o[nb][r] = 0.f;
    float mrow[2] = {-1e30f, -1e30f};
    float lrow[2] = {0.f, 0.f};

    const int b_row = (lane & 7) + ((lane >> 4) & 1) * 8;  // K (non-trans)
    const int b_kp  = ((lane >> 3) & 1) * 4;
    const int v_row = (lane & 7) + ((lane >> 3) & 1) * 8;  // V (trans)
    const int v_dp  = ((lane >> 4) & 1) * 4;

    for (int kt = 0; kt < NKV/64; kt++) {
        CP_WAIT0();
        __syncthreads();            // copy visible; prev compute done
        if (kt + 1 < NKV/64) issue_copy((kt + 1) & 1, kt + 1);

        uint32_t base = sbu + (uint32_t)((kt & 1)*4*STG)*4u;
        uint32_t uKhi = base;
        uint32_t uKlo = base + STG*4u;
        uint32_t uVhi = base + 2*STG*4u;
        uint32_t uVlo = base + 3*STG*4u;

        // ---- S = Q K^T (3-pass split) ----
        float s[8][4];
        #pragma unroll
        for (int nb = 0; nb < 8; nb++)
            #pragma unroll
            for (int r = 0; r < 4; r++) s[nb][r] = 0.f;
        #pragma unroll
        for (int kb = 0; kb < 4; kb++) {
            #pragma unroll
            for (int p = 0; p < 4; p++) {
                uint32_t off = ((p*16 + b_row)*KST + kb*8 + b_kp) * 4u;
                uint32_t bh0[2], bh1[2], bl0[2], bl1[2];
                ldsm_x4(bh0[0], bh0[1], bh1[0], bh1[1], uKhi + off);
                ldsm_x4(bl0[0], bl0[1], bl1[0], bl1[1], uKlo + off);
                mma_bf16(s[2*p],   qh[kb], bh0);
                mma_bf16(s[2*p+1], qh[kb], bh1);
                mma_bf16(s[2*p],   ql[kb], bh0);
                mma_bf16(s[2*p+1], ql[kb], bh1);
                mma_bf16(s[2*p],   qh[kb], bl0);
                mma_bf16(s[2*p+1], qh[kb], bl1);
            }
        }

        // ---- online softmax on fragments ----
        float mx0 = s[0][0], mx1 = s[0][2];
        #pragma unroll
        for (int nb = 0; nb < 8; nb++) {
            mx0 = fmaxf(mx0, fmaxf(s[nb][0], s[nb][1]));
            mx1 = fmaxf(mx1, fmaxf(s[nb][2], s[nb][3]));
        }
        mx0 = fmaxf(mx0, __shfl_xor_sync(0xffffffffu, mx0, 1));
        mx0 = fmaxf(mx0, __shfl_xor_sync(0xffffffffu, mx0, 2));
        mx1 = fmaxf(mx1, __shfl_xor_sync(0xffffffffu, mx1, 1));
        mx1 = fmaxf(mx1, __shfl_xor_sync(0xffffffffu, mx1, 2));
        float mn0 = fmaxf(mrow[0], mx0);
        float mn1 = fmaxf(mrow[1], mx1);
        float al0 = ex2f(mrow[0] - mn0);
        float al1 = ex2f(mrow[1] - mn1);
        mrow[0] = mn0; mrow[1] = mn1;

        float sum0 = 0.f, sum1 = 0.f;
        #pragma unroll
        for (int nb = 0; nb < 8; nb++) {
            s[nb][0] = ex2f(s[nb][0] - mn0);
            s[nb][1] = ex2f(s[nb][1] - mn0);
            s[nb][2] = ex2f(s[nb][2] - mn1);
            s[nb][3] = ex2f(s[nb][3] - mn1);
            sum0 += s[nb][0] + s[nb][1];
            sum1 += s[nb][2] + s[nb][3];
        }
        sum0 += __shfl_xor_sync(0xffffffffu, sum0, 1);
        sum0 += __shfl_xor_sync(0xffffffffu, sum0, 2);
        sum1 += __shfl_xor_sync(0xffffffffu, sum1, 1);
        sum1 += __shfl_xor_sync(0xffffffffu, sum1, 2);
        lrow[0] = lrow[0]*al0 + sum0;
        lrow[1] = lrow[1]*al1 + sum1;

        #pragma unroll
        for (int nb = 0; nb < 8; nb++) {
            o[nb][0] *= al0; o[nb][1] *= al0;
            o[nb][2] *= al1; o[nb][3] *= al1;
        }

        // ---- O += P V (pack P per-kb; V b-frags via ldmatrix.trans) ----
        #pragma unroll
        for (int kb = 0; kb < 4; kb++) {
            uint32_t ph[4], pl[4];
            split2(s[2*kb][0],   s[2*kb][1],   ph[0], pl[0]);
            split2(s[2*kb][2],   s[2*kb][3],   ph[1], pl[1]);
            split2(s[2*kb+1][0], s[2*kb+1][1], ph[2], pl[2]);
            split2(s[2*kb+1][2], s[2*kb+1][3], ph[3], pl[3]);
            #pragma unroll
            for (int p = 0; p < 4; p++) {
                uint32_t off = ((kb*16 + v_row)*KST + p*8 + v_dp) * 4u;
                uint32_t vh0[2], vh1[2], vl0[2], vl1[2];
                ldsm_x4_t(vh0[0], vh0[1], vh1[0], vh1[1], uVhi + off);
                ldsm_x4_t(vl0[0], vl0[1], vl1[0], vl1[1], uVlo + off);
                mma_bf16(o[2*p],   ph, vh0);
                mma_bf16(o[2*p+1], ph, vh1);
                mma_bf16(o[2*p],   pl, vh0);
                mma_bf16(o[2*p+1], pl, vh1);
                mma_bf16(o[2*p],   ph, vl0);
                mma_bf16(o[2*p+1], ph, vl1);
            }
        }
    }

    // ---- normalize and write out [t][d] ----
    float inv0 = 1.0f / lrow[0];
    float inv1 = 1.0f / lrow[1];
    int rowa = qt*64 + warp*16 + qr;
    #pragma unroll
    for (int nb = 0; nb < 8; nb++) {
        int col = h*DH + nb*8 + 2*cq;
        *(float2*)(g_ob + (size_t)rowa*ND + col) =
            make_float2(o[nb][0]*inv0, o[nb][1]*inv0);
        *(float2*)(g_ob + (size_t)(rowa+8)*ND + col) =
            make_float2(o[nb][2]*inv1, o[nb][3]*inv1);
    }
}

// ---------------------------------------------------------------------------
// Kernel 3 (per batch): output projection + bias, 64x128 tiles.
// Grid (NT/64, ND/128) = (32, 8), 256 threads.
// ---------------------------------------------------------------------------
__global__ __launch_bounds__(256) void out_mma_kernel(
    const float* __restrict__ W, const float* __restrict__ bias,
    float* __restrict__ Yb)
{
    __shared__ GemmSmemT<2,4> s;
    float acc[2][4][4];
    gemm_core_t<2,4>(g_ob, W, ND, s, acc);

    const int lane   = threadIdx.x & 31;
    const int wid    = threadIdx.x >> 5;
    const int warp_m = (wid & 1) * 32;
    const int warp_n = (wid >> 1) * 32;

    const int ncol0 = blockIdx.y*128 + warp_n + 2*(lane & 3);
    float2 bset[4];
    #pragma unroll
    for (int ni = 0; ni < 4; ni++)
        bset[ni] = make_float2(bias[ncol0 + ni*8], bias[ncol0 + ni*8 + 1]);

    #pragma unroll
    for (int mi = 0; mi < 2; mi++) {
        #pragma unroll
        for (int half = 0; half < 2; half++) {
            int grow = blockIdx.x*64 + warp_m + mi*16 + (lane >> 2) + half*8;
            float* dst = Yb + (size_t)grow*ND + ncol0;
            #pragma unroll
            for (int ni = 0; ni < 4; ni++) {
                float2 v = make_float2(acc[mi][ni][2*half]   + bset[ni].x,
                                       acc[mi][ni][2*half+1] + bset[ni].y);
                *(float2*)(dst + ni*8) = v;
            }
        }
    }
}

// ---------------------------------------------------------------------------
extern "C" void kernel_launch(void* const* d_in, const int* in_sizes, int n_in,
                              void* d_out, int out_size)
{
    // Identify inputs by element count:
    //   x 4194304, w_qkv 3145728, w_out 1048576, b_out 1024, memory 524288
    const float *x = nullptr, *w_qkv = nullptr, *w_out = nullptr,
                *b_out = nullptr, *memory = nullptr;
    for (int i = 0; i < n_in; i++) {
        switch (in_sizes[i]) {
            case 4194304: x      = (const float*)d_in[i]; break;
            case 3145728: w_qkv  = (const float*)d_in[i]; break;
            case 1048576: w_out  = (const float*)d_in[i]; break;
            case 1024:    b_out  = (const float*)d_in[i]; break;
            case 524288:  memory = (const float*)d_in[i]; break;
            default: break;
        }
    }
    float* out = (float*)d_out;

    cudaFuncSetAttribute(attn_mma_kernel,
                         cudaFuncAttributeMaxDynamicSharedMemorySize,
                         ATTN_SMEM_BYTES);

    // Pack memory K/V once (keys [0, 512) for every head, both batches).
    pack_memory_kernel<<<NMEM*ND/2/256, 256>>>(memory);

    for (int b = 0; b < NB; b++) {
        const float* xb = x + (size_t)b*NT*ND;
        float*       yb = out + (size_t)b*NT*ND;
        qkv_mma_kernel<<<dim3(NT/128, 3*ND/128), 256>>>(xb, w_qkv);      // 16 x 24
        attn_mma_kernel<<<dim3(NT/64, NH), 128, ATTN_SMEM_BYTES>>>();    // 32 x 16
        out_mma_kernel<<<dim3(NT/64, ND/128), 256>>>(w_out, b_out, yb);  // 32 x 8
    }
}